// round 1
// baseline (speedup 1.0000x reference)
#include <cuda_runtime.h>
#include <float.h>

#define N_NODES 8192
#define F_IN    256
#define F_OUT   128

// ---------------- scratch (allocation-free: device globals) ----------------
__device__ float g_h [N_NODES * F_OUT];
__device__ float g_s [N_NODES];
__device__ float g_t [N_NODES];
__device__ float g_m [N_NODES];
__device__ float g_rz[N_NODES];

// ---------------- kernel 1: h = x @ W  (8192x256 @ 256x128) ----------------
#define GH_BM 64
#define GH_BK 16
__global__ void __launch_bounds__(256) k_gemm_h(const float* __restrict__ x,
                                                const float* __restrict__ W,
                                                float* __restrict__ h) {
    __shared__ float As[GH_BK][GH_BM];   // transposed x tile
    __shared__ float Bs[GH_BK][F_OUT];
    const int tid = threadIdx.x;
    const int rowBase = blockIdx.x * GH_BM;
    const int tx = tid & 31;          // column group (4 cols)
    const int ty = tid >> 5;          // row group (8 rows)
    const int m0 = ty * 8;
    const int n0 = tx * 4;

    float acc[8][4];
#pragma unroll
    for (int i = 0; i < 8; i++)
#pragma unroll
        for (int j = 0; j < 4; j++) acc[i][j] = 0.f;

    for (int k0 = 0; k0 < F_IN; k0 += GH_BK) {
        // A tile: 64x16 = 256 float4, one per thread
        {
            int r  = tid >> 2;
            int kc = (tid & 3) * 4;
            float4 v = *(const float4*)&x[(rowBase + r) * F_IN + k0 + kc];
            As[kc + 0][r] = v.x; As[kc + 1][r] = v.y;
            As[kc + 2][r] = v.z; As[kc + 3][r] = v.w;
        }
        // B tile: 16x128 = 512 float4, two per thread
#pragma unroll
        for (int rep = 0; rep < 2; rep++) {
            int i4 = tid + rep * 256;
            int kk = i4 >> 5;
            int nn = (i4 & 31) * 4;
            *(float4*)&Bs[kk][nn] = *(const float4*)&W[(k0 + kk) * F_OUT + nn];
        }
        __syncthreads();
#pragma unroll
        for (int k = 0; k < GH_BK; k++) {
            float a_reg[8];
#pragma unroll
            for (int i = 0; i < 8; i++) a_reg[i] = As[k][m0 + i];
            float4 b = *(const float4*)&Bs[k][n0];
#pragma unroll
            for (int i = 0; i < 8; i++) {
                acc[i][0] += a_reg[i] * b.x;
                acc[i][1] += a_reg[i] * b.y;
                acc[i][2] += a_reg[i] * b.z;
                acc[i][3] += a_reg[i] * b.w;
            }
        }
        __syncthreads();
    }
#pragma unroll
    for (int i = 0; i < 8; i++) {
        float4 v = make_float4(acc[i][0], acc[i][1], acc[i][2], acc[i][3]);
        *(float4*)&h[(rowBase + m0 + i) * F_OUT + n0] = v;
    }
}

// ---------------- kernel 2: s = h@a1, t = h@a2 (one warp per row) ----------
__global__ void __launch_bounds__(256) k_st(const float* __restrict__ h,
                                            const float* __restrict__ a,
                                            float* __restrict__ s,
                                            float* __restrict__ t) {
    const int row  = blockIdx.x * 8 + (threadIdx.x >> 5);
    const int lane = threadIdx.x & 31;
    float4 hv  = *(const float4*)&h[row * F_OUT + lane * 4];
    float4 a1v = *(const float4*)&a[lane * 4];
    float4 a2v = *(const float4*)&a[F_OUT + lane * 4];
    float ss = hv.x * a1v.x + hv.y * a1v.y + hv.z * a1v.z + hv.w * a1v.w;
    float tt = hv.x * a2v.x + hv.y * a2v.y + hv.z * a2v.z + hv.w * a2v.w;
#pragma unroll
    for (int off = 16; off > 0; off >>= 1) {
        ss += __shfl_xor_sync(0xffffffffu, ss, off);
        tt += __shfl_xor_sync(0xffffffffu, tt, off);
    }
    if (lane == 0) { s[row] = ss; t[row] = tt; }
}

// ---------------- kernel 3: per-row softmax stats (max, 1/Z) ---------------
// one warp per row; int4-vectorized adj reads (DRAM-bound: 256MB)
__global__ void __launch_bounds__(256) k_stats(const int* __restrict__ adj,
                                               const float* __restrict__ s,
                                               const float* __restrict__ t,
                                               float* __restrict__ m_out,
                                               float* __restrict__ rz_out) {
    const int row  = blockIdx.x * 8 + (threadIdx.x >> 5);
    const int lane = threadIdx.x & 31;
    const float si = s[row];
    const int4* arow = (const int4*)(adj + (size_t)row * N_NODES);

    float m = -FLT_MAX;
    float z = 0.f;
#pragma unroll 4
    for (int it = 0; it < N_NODES / 128; it++) {
        int  j0 = it * 128 + lane * 4;
        int4 av = arow[it * 32 + lane];
        float4 tv = *(const float4*)&t[j0];
        float ev[4];
        int   mk[4] = { av.x, av.y, av.z, av.w };
        ev[0] = si + tv.x; ev[1] = si + tv.y; ev[2] = si + tv.z; ev[3] = si + tv.w;
#pragma unroll
        for (int q = 0; q < 4; q++) {
            if (mk[q] > 0) {
                float e = ev[q];
                e = fmaxf(e, 0.2f * e);       // leaky_relu, alpha=0.2
                if (e > m) {
                    z = z * __expf(m - e) + 1.f;
                    m = e;
                } else {
                    z += __expf(e - m);
                }
            }
        }
    }
    // warp-combine (m,z)
#pragma unroll
    for (int off = 16; off > 0; off >>= 1) {
        float mo = __shfl_xor_sync(0xffffffffu, m, off);
        float zo = __shfl_xor_sync(0xffffffffu, z, off);
        float mn = fmaxf(m, mo);
        z = z * __expf(m - mn) + zo * __expf(mo - mn);
        m = mn;
    }
    if (lane == 0) { m_out[row] = m; rz_out[row] = 1.f / z; }
}

// ---------------- kernel 4: out = P @ h with P computed on the fly ---------
// BM=32 rows, BN=128 (full Fout), BK=32; 256 threads, 4x4 register tile
#define P2_BM 32
#define P2_BK 32
__global__ void __launch_bounds__(256) k_av(const int* __restrict__ adj,
                                            const float* __restrict__ h,
                                            const float* __restrict__ s,
                                            const float* __restrict__ t,
                                            const float* __restrict__ mrow,
                                            const float* __restrict__ rz,
                                            float* __restrict__ out) {
    __shared__ float Ps[P2_BM][P2_BK + 1];   // [m][k], +1 pad
    __shared__ float Hs[P2_BK][F_OUT];

    const int tid = threadIdx.x;
    const int rowBase = blockIdx.x * P2_BM;
    const int tx = tid & 31;        // k index for P fill / column group for GEMM
    const int ty = tid >> 5;        // 0..7
    const int n0 = tx * 4;
    const int m0 = ty * 4;

    // per-thread row constants for the 4 P rows this thread fills (rows ty+8i)
    float sf[4], mf[4], rf[4];
#pragma unroll
    for (int i = 0; i < 4; i++) {
        int r = rowBase + ty + i * 8;
        sf[i] = s[r]; mf[i] = mrow[r]; rf[i] = rz[r];
    }

    float acc[4][4];
#pragma unroll
    for (int i = 0; i < 4; i++)
#pragma unroll
        for (int j = 0; j < 4; j++) acc[i][j] = 0.f;

    for (int k0 = 0; k0 < N_NODES; k0 += P2_BK) {
        // ---- fill P tile (32x32): thread handles rows ty+8i, col tx ----
        const int j = k0 + tx;
        const float tj = t[j];
#pragma unroll
        for (int i = 0; i < 4; i++) {
            int mr = ty + i * 8;
            int av = adj[(size_t)(rowBase + mr) * N_NODES + j];
            float p = 0.f;
            if (av > 0) {
                float e = sf[i] + tj;
                e = fmaxf(e, 0.2f * e);
                p = __expf(e - mf[i]) * rf[i];
            }
            Ps[mr][tx] = p;
        }
        // ---- fill H tile (32x128): 1024 float4, 4 per thread ----
#pragma unroll
        for (int i = 0; i < 4; i++) {
            int i4 = tid + i * 256;
            int kk = i4 >> 5;
            int nn = (i4 & 31) * 4;
            *(float4*)&Hs[kk][nn] = *(const float4*)&h[(k0 + kk) * F_OUT + nn];
        }
        __syncthreads();
        // ---- GEMM inner loop ----
#pragma unroll
        for (int k = 0; k < P2_BK; k++) {
            float4 b = *(const float4*)&Hs[k][n0];
            float a0 = Ps[m0 + 0][k];
            float a1 = Ps[m0 + 1][k];
            float a2 = Ps[m0 + 2][k];
            float a3 = Ps[m0 + 3][k];
            acc[0][0] += a0 * b.x; acc[0][1] += a0 * b.y; acc[0][2] += a0 * b.z; acc[0][3] += a0 * b.w;
            acc[1][0] += a1 * b.x; acc[1][1] += a1 * b.y; acc[1][2] += a1 * b.z; acc[1][3] += a1 * b.w;
            acc[2][0] += a2 * b.x; acc[2][1] += a2 * b.y; acc[2][2] += a2 * b.z; acc[2][3] += a2 * b.w;
            acc[3][0] += a3 * b.x; acc[3][1] += a3 * b.y; acc[3][2] += a3 * b.z; acc[3][3] += a3 * b.w;
        }
        __syncthreads();
    }
#pragma unroll
    for (int i = 0; i < 4; i++) {
        float4 v = make_float4(acc[i][0], acc[i][1], acc[i][2], acc[i][3]);
        *(float4*)&out[(size_t)(rowBase + m0 + i) * F_OUT + n0] = v;
    }
}

// ---------------- launch ----------------
extern "C" void kernel_launch(void* const* d_in, const int* in_sizes, int n_in,
                              void* d_out, int out_size) {
    const float* x   = (const float*)d_in[0];
    const int*   adj = (const int*)  d_in[1];
    const float* W   = (const float*)d_in[2];
    const float* a   = (const float*)d_in[3];
    float* out = (float*)d_out;

    float *h, *s, *t, *m, *rz;
    cudaGetSymbolAddress((void**)&h,  g_h);
    cudaGetSymbolAddress((void**)&s,  g_s);
    cudaGetSymbolAddress((void**)&t,  g_t);
    cudaGetSymbolAddress((void**)&m,  g_m);
    cudaGetSymbolAddress((void**)&rz, g_rz);

    k_gemm_h<<<N_NODES / GH_BM, 256>>>(x, W, h);
    k_st    <<<N_NODES / 8,     256>>>(h, a, s, t);
    k_stats <<<N_NODES / 8,     256>>>(adj, s, t, m, rz);
    k_av    <<<N_NODES / P2_BM, 256>>>(adj, h, s, t, m, rz, out);
}

// round 3
// speedup vs baseline: 3.1765x; 3.1765x over previous
#include <cuda_runtime.h>
#include <cuda_fp16.h>
#include <float.h>
#include <stdint.h>

#define N_NODES 8192
#define F_IN    256
#define F_OUT   128

// ---------------- scratch (allocation-free: device globals) ----------------
__device__ float  g_h   [N_NODES * F_OUT];
__device__ __half g_h16 [N_NODES * F_OUT];        // fp16 copy, natural layout
__device__ float  g_s   [N_NODES];
__device__ float  g_t   [N_NODES];
__device__ float  g_part[2 * N_NODES * F_OUT];    // K-split numerator partials
__device__ float  g_zp  [2 * N_NODES];            // K-split Z partials

// ---------------- warp-mma helpers (baseline PTX, sm_80+) -----------------
__device__ __forceinline__ void ldsm_x4(uint32_t* r, uint32_t addr) {
    asm volatile("ldmatrix.sync.aligned.m8n8.x4.shared.b16 {%0,%1,%2,%3}, [%4];"
                 : "=r"(r[0]), "=r"(r[1]), "=r"(r[2]), "=r"(r[3]) : "r"(addr));
}
__device__ __forceinline__ void ldsm_x4_t(uint32_t* r, uint32_t addr) {
    asm volatile("ldmatrix.sync.aligned.m8n8.x4.trans.shared.b16 {%0,%1,%2,%3}, [%4];"
                 : "=r"(r[0]), "=r"(r[1]), "=r"(r[2]), "=r"(r[3]) : "r"(addr));
}
__device__ __forceinline__ void mma16816(float* c, const uint32_t* a,
                                         uint32_t b0, uint32_t b1) {
    asm volatile(
        "mma.sync.aligned.m16n8k16.row.col.f32.f16.f16.f32 "
        "{%0,%1,%2,%3}, {%4,%5,%6,%7}, {%8,%9}, {%0,%1,%2,%3};"
        : "+f"(c[0]), "+f"(c[1]), "+f"(c[2]), "+f"(c[3])
        : "r"(a[0]), "r"(a[1]), "r"(a[2]), "r"(a[3]), "r"(b0), "r"(b1));
}

// ---------------- kernel 1: h = x @ W  (8192x256 @ 256x128) ----------------
#define GH_BM 64
#define GH_BK 16
__global__ void __launch_bounds__(256) k_gemm_h(const float* __restrict__ x,
                                                const float* __restrict__ W,
                                                float* __restrict__ h,
                                                __half* __restrict__ h16) {
    __shared__ float As[GH_BK][GH_BM];
    __shared__ float Bs[GH_BK][F_OUT];
    const int tid = threadIdx.x;
    const int rowBase = blockIdx.x * GH_BM;
    const int tx = tid & 31;
    const int ty = tid >> 5;
    const int m0 = ty * 8;
    const int n0 = tx * 4;

    float acc[8][4];
#pragma unroll
    for (int i = 0; i < 8; i++)
#pragma unroll
        for (int j = 0; j < 4; j++) acc[i][j] = 0.f;

    for (int k0 = 0; k0 < F_IN; k0 += GH_BK) {
        {
            int r  = tid >> 2;
            int kc = (tid & 3) * 4;
            float4 v = *(const float4*)&x[(rowBase + r) * F_IN + k0 + kc];
            As[kc + 0][r] = v.x; As[kc + 1][r] = v.y;
            As[kc + 2][r] = v.z; As[kc + 3][r] = v.w;
        }
#pragma unroll
        for (int rep = 0; rep < 2; rep++) {
            int i4 = tid + rep * 256;
            int kk = i4 >> 5;
            int nn = (i4 & 31) * 4;
            *(float4*)&Bs[kk][nn] = *(const float4*)&W[(k0 + kk) * F_OUT + nn];
        }
        __syncthreads();
#pragma unroll
        for (int k = 0; k < GH_BK; k++) {
            float a_reg[8];
#pragma unroll
            for (int i = 0; i < 8; i++) a_reg[i] = As[k][m0 + i];
            float4 b = *(const float4*)&Bs[k][n0];
#pragma unroll
            for (int i = 0; i < 8; i++) {
                acc[i][0] += a_reg[i] * b.x;
                acc[i][1] += a_reg[i] * b.y;
                acc[i][2] += a_reg[i] * b.z;
                acc[i][3] += a_reg[i] * b.w;
            }
        }
        __syncthreads();
    }
#pragma unroll
    for (int i = 0; i < 8; i++) {
        float4 v = make_float4(acc[i][0], acc[i][1], acc[i][2], acc[i][3]);
        size_t idx = (size_t)(rowBase + m0 + i) * F_OUT + n0;
        *(float4*)&h[idx] = v;
        __half2 p01 = __floats2half2_rn(v.x, v.y);
        __half2 p23 = __floats2half2_rn(v.z, v.w);
        uint2 hv;
        hv.x = *reinterpret_cast<uint32_t*>(&p01);
        hv.y = *reinterpret_cast<uint32_t*>(&p23);
        *reinterpret_cast<uint2*>(&h16[idx]) = hv;
    }
}

// ---------------- kernel 2: s = h@a1, t = h@a2 -----------------------------
__global__ void __launch_bounds__(256) k_st(const float* __restrict__ h,
                                            const float* __restrict__ a,
                                            float* __restrict__ s,
                                            float* __restrict__ t) {
    const int row  = blockIdx.x * 8 + (threadIdx.x >> 5);
    const int lane = threadIdx.x & 31;
    float4 hv  = *(const float4*)&h[row * F_OUT + lane * 4];
    float4 a1v = *(const float4*)&a[lane * 4];
    float4 a2v = *(const float4*)&a[F_OUT + lane * 4];
    float ss = hv.x * a1v.x + hv.y * a1v.y + hv.z * a1v.z + hv.w * a1v.w;
    float tt = hv.x * a2v.x + hv.y * a2v.y + hv.z * a2v.z + hv.w * a2v.w;
#pragma unroll
    for (int off = 16; off > 0; off >>= 1) {
        ss += __shfl_xor_sync(0xffffffffu, ss, off);
        tt += __shfl_xor_sync(0xffffffffu, tt, off);
    }
    if (lane == 0) { s[row] = ss; t[row] = tt; }
}

// ---------------- kernel 3: fused P-compute + P@H (HMMA) + Z ---------------
// grid = 128: (bid>>1) = M-block of 128 rows, (bid&1) = K half (4096 nodes).
// Single pass over adj: P~ = exp(lrelu(s+t) - 8) (unnormalized), Z summed in
// fp32 registers. 8 warps, each owns m16 x n128 of the accumulator.
#define BK     64
#define NCHUNK (4096 / BK)
#define PS_STRIDE 72     // fp16 elems per row (64 + 8 pad) -> 144B, LDSM-safe
#define HS_STRIDE 136    // fp16 elems per row (128 + 8 pad) -> 272B, LDSM-safe
#define SHIFT_C 8.0f

__global__ void __launch_bounds__(256) k_av_mma(const int* __restrict__ adj,
                                                const __half* __restrict__ h16,
                                                const float* __restrict__ s,
                                                const float* __restrict__ t,
                                                float* __restrict__ part,
                                                float* __restrict__ zp) {
    __shared__ __half Ps[128 * PS_STRIDE];
    __shared__ __half Hs[BK * HS_STRIDE];

    const int tid  = threadIdx.x;
    const int wid  = tid >> 5;
    const int lane = tid & 31;
    const int rowBase = (blockIdx.x >> 1) * 128;
    const int kh      = blockIdx.x & 1;
    const int jBase   = kh * 4096;

    // P-fill mapping: thread owns row (tid>>1), col half (tid&1)*32
    const int prow  = tid >> 1;
    const int chalf = (tid & 1) * 32;
    const float sR  = s[rowBase + prow];
    const int4* arow = (const int4*)(adj + (size_t)(rowBase + prow) * N_NODES);

    // ldmatrix source addresses
    const uint32_t psBase = (uint32_t)__cvta_generic_to_shared(Ps);
    const uint32_t hsBase = (uint32_t)__cvta_generic_to_shared(Hs);
    const uint32_t aAddr0 = psBase + (uint32_t)((wid * 16 + (lane & 15)) * (PS_STRIDE * 2))
                                   + (uint32_t)((lane >> 4) * 16);

    float acc[16][4];
#pragma unroll
    for (int i = 0; i < 16; i++)
#pragma unroll
        for (int j = 0; j < 4; j++) acc[i][j] = 0.f;
    float z = 0.f;

    for (int c = 0; c < NCHUNK; c++) {
        const int j0 = jBase + c * BK;
        __syncthreads();   // previous chunk's tiles fully consumed

        // ---- P~ tile [128 x 64] fp16 + Z accumulation ----
        {
            const int4* ap = arow + (j0 + chalf) / 4;
            __half* pr = Ps + prow * PS_STRIDE + chalf;
#pragma unroll
            for (int q = 0; q < 8; q++) {
                int4   av = ap[q];
                float4 tv = *(const float4*)&t[j0 + chalf + q * 4];
                float e0 = sR + tv.x; e0 = fmaxf(e0, 0.2f * e0);
                float e1 = sR + tv.y; e1 = fmaxf(e1, 0.2f * e1);
                float e2 = sR + tv.z; e2 = fmaxf(e2, 0.2f * e2);
                float e3 = sR + tv.w; e3 = fmaxf(e3, 0.2f * e3);
                float p0 = (av.x > 0) ? __expf(e0 - SHIFT_C) : 0.f;
                float p1 = (av.y > 0) ? __expf(e1 - SHIFT_C) : 0.f;
                float p2 = (av.z > 0) ? __expf(e2 - SHIFT_C) : 0.f;
                float p3 = (av.w > 0) ? __expf(e3 - SHIFT_C) : 0.f;
                z += (p0 + p1) + (p2 + p3);
                __half2 h01 = __floats2half2_rn(p0, p1);
                __half2 h23 = __floats2half2_rn(p2, p3);
                uint2 stv;
                stv.x = *reinterpret_cast<uint32_t*>(&h01);
                stv.y = *reinterpret_cast<uint32_t*>(&h23);
                *reinterpret_cast<uint2*>(pr + q * 4) = stv;
            }
        }
        // ---- H tile [64(k) x 128(n)] fp16, natural layout ----
        {
#pragma unroll
            for (int i = 0; i < 4; i++) {
                int idx = tid + i * 256;       // 1024 granules of 16B
                int r = idx >> 4;
                int g = idx & 15;
                const uint4 v = *reinterpret_cast<const uint4*>(
                    h16 + (size_t)(j0 + r) * F_OUT + g * 8);
                *reinterpret_cast<uint4*>(Hs + r * HS_STRIDE + g * 8) = v;
            }
        }
        __syncthreads();

        // ---- 4 k-tiles x 16 n-tiles of m16n8k16 ----
#pragma unroll
        for (int kt = 0; kt < 4; kt++) {
            uint32_t a[4];
            ldsm_x4(a, aAddr0 + kt * 32);
            const uint32_t bRowAddr = hsBase
                + (uint32_t)((kt * 16 + (lane & 15)) * (HS_STRIDE * 2))
                + (uint32_t)((lane >> 4) * 16);
#pragma unroll
            for (int np = 0; np < 8; np++) {
                uint32_t b[4];
                ldsm_x4_t(b, bRowAddr + np * 32);
                mma16816(acc[np * 2 + 0], a, b[0], b[1]);
                mma16816(acc[np * 2 + 1], a, b[2], b[3]);
            }
        }
    }

    // ---- Z: combine the two column-halves of each row, store partial ----
    z += __shfl_xor_sync(0xffffffffu, z, 1);
    if ((tid & 1) == 0) zp[kh * N_NODES + rowBase + prow] = z;

    // ---- numerator partial: fragment scatter (float2 stores) ----
    float* partOut = part + (size_t)kh * N_NODES * F_OUT;
    const int r0 = rowBase + wid * 16 + (lane >> 2);
    const int c0 = (lane & 3) * 2;
#pragma unroll
    for (int nt = 0; nt < 16; nt++) {
        *(float2*)&partOut[(size_t)r0 * F_OUT + nt * 8 + c0] =
            make_float2(acc[nt][0], acc[nt][1]);
        *(float2*)&partOut[(size_t)(r0 + 8) * F_OUT + nt * 8 + c0] =
            make_float2(acc[nt][2], acc[nt][3]);
    }
}

// ---------------- kernel 4: out = (n0+n1) / (z0+z1) ------------------------
__global__ void __launch_bounds__(256) k_reduce(const float* __restrict__ part,
                                                const float* __restrict__ zp,
                                                float* __restrict__ out) {
    int i = (blockIdx.x * 256 + threadIdx.x) * 4;
    int row = i / F_OUT;
    float zinv = 1.f / (zp[row] + zp[N_NODES + row]);
    float4 a = *(const float4*)&part[i];
    float4 b = *(const float4*)&part[N_NODES * F_OUT + i];
    float4 v = make_float4((a.x + b.x) * zinv, (a.y + b.y) * zinv,
                           (a.z + b.z) * zinv, (a.w + b.w) * zinv);
    *(float4*)&out[i] = v;
}

// ---------------- launch ----------------
extern "C" void kernel_launch(void* const* d_in, const int* in_sizes, int n_in,
                              void* d_out, int out_size) {
    const float* x   = (const float*)d_in[0];
    const int*   adj = (const int*)  d_in[1];
    const float* W   = (const float*)d_in[2];
    const float* a   = (const float*)d_in[3];
    float* out = (float*)d_out;

    float *h, *s, *t, *part, *zp;
    __half* h16;
    cudaGetSymbolAddress((void**)&h,    g_h);
    cudaGetSymbolAddress((void**)&h16,  g_h16);
    cudaGetSymbolAddress((void**)&s,    g_s);
    cudaGetSymbolAddress((void**)&t,    g_t);
    cudaGetSymbolAddress((void**)&part, g_part);
    cudaGetSymbolAddress((void**)&zp,   g_zp);

    k_gemm_h <<<N_NODES / GH_BM, 256>>>(x, W, h, h16);
    k_st     <<<N_NODES / 8,     256>>>(h, a, s, t);
    k_av_mma <<<128, 256>>>(adj, h16, s, t, part, zp);
    k_reduce <<<N_NODES * F_OUT / 1024, 256>>>(part, zp, out);
}

// round 4
// speedup vs baseline: 3.2786x; 1.0322x over previous
#include <cuda_runtime.h>
#include <cuda_fp16.h>
#include <float.h>
#include <stdint.h>

#define N_NODES 8192
#define F_IN    256
#define F_OUT   128

// ---------------- scratch (allocation-free: device globals) ----------------
__device__ __half g_h16 [N_NODES * F_OUT];        // fp16 h, natural layout
__device__ float  g_s   [N_NODES];
__device__ float  g_t   [N_NODES];
__device__ float  g_E1  [N_NODES];                // exp(t - 4)
__device__ float  g_E2  [N_NODES];                // exp(0.2t - 4)
__device__ float  g_part[2 * N_NODES * F_OUT];    // K-split numerator partials
__device__ float  g_zp  [2 * N_NODES];            // K-split Z partials

// ---------------- warp-mma helpers (baseline PTX, sm_80+) -----------------
__device__ __forceinline__ void ldsm_x4(uint32_t* r, uint32_t addr) {
    asm volatile("ldmatrix.sync.aligned.m8n8.x4.shared.b16 {%0,%1,%2,%3}, [%4];"
                 : "=r"(r[0]), "=r"(r[1]), "=r"(r[2]), "=r"(r[3]) : "r"(addr));
}
__device__ __forceinline__ void ldsm_x4_t(uint32_t* r, uint32_t addr) {
    asm volatile("ldmatrix.sync.aligned.m8n8.x4.trans.shared.b16 {%0,%1,%2,%3}, [%4];"
                 : "=r"(r[0]), "=r"(r[1]), "=r"(r[2]), "=r"(r[3]) : "r"(addr));
}
__device__ __forceinline__ void mma16816(float* c, const uint32_t* a,
                                         uint32_t b0, uint32_t b1) {
    asm volatile(
        "mma.sync.aligned.m16n8k16.row.col.f32.f16.f16.f32 "
        "{%0,%1,%2,%3}, {%4,%5,%6,%7}, {%8,%9}, {%0,%1,%2,%3};"
        : "+f"(c[0]), "+f"(c[1]), "+f"(c[2]), "+f"(c[3])
        : "r"(a[0]), "r"(a[1]), "r"(a[2]), "r"(a[3]), "r"(b0), "r"(b1));
}

// ---------------- kernel 1: h16 = fp16(x@W);  s = h@a1, t = h@a2 ----------
#define GH_BM 64
#define GH_BK 16
__global__ void __launch_bounds__(256) k_gemm_h(const float* __restrict__ x,
                                                const float* __restrict__ W,
                                                const float* __restrict__ a,
                                                __half* __restrict__ h16,
                                                float* __restrict__ s,
                                                float* __restrict__ t) {
    __shared__ float As[GH_BK][GH_BM];
    __shared__ float Bs[GH_BK][F_OUT];
    const int tid = threadIdx.x;
    const int rowBase = blockIdx.x * GH_BM;
    const int tx = tid & 31;
    const int ty = tid >> 5;
    const int m0 = ty * 8;
    const int n0 = tx * 4;

    float acc[8][4];
#pragma unroll
    for (int i = 0; i < 8; i++)
#pragma unroll
        for (int j = 0; j < 4; j++) acc[i][j] = 0.f;

    for (int k0 = 0; k0 < F_IN; k0 += GH_BK) {
        {
            int r  = tid >> 2;
            int kc = (tid & 3) * 4;
            float4 v = *(const float4*)&x[(rowBase + r) * F_IN + k0 + kc];
            As[kc + 0][r] = v.x; As[kc + 1][r] = v.y;
            As[kc + 2][r] = v.z; As[kc + 3][r] = v.w;
        }
#pragma unroll
        for (int rep = 0; rep < 2; rep++) {
            int i4 = tid + rep * 256;
            int kk = i4 >> 5;
            int nn = (i4 & 31) * 4;
            *(float4*)&Bs[kk][nn] = *(const float4*)&W[(k0 + kk) * F_OUT + nn];
        }
        __syncthreads();
#pragma unroll
        for (int k = 0; k < GH_BK; k++) {
            float a_reg[8];
#pragma unroll
            for (int i = 0; i < 8; i++) a_reg[i] = As[k][m0 + i];
            float4 b = *(const float4*)&Bs[k][n0];
#pragma unroll
            for (int i = 0; i < 8; i++) {
                acc[i][0] += a_reg[i] * b.x;
                acc[i][1] += a_reg[i] * b.y;
                acc[i][2] += a_reg[i] * b.z;
                acc[i][3] += a_reg[i] * b.w;
            }
        }
        __syncthreads();
    }
    // h16 store
#pragma unroll
    for (int i = 0; i < 8; i++) {
        size_t idx = (size_t)(rowBase + m0 + i) * F_OUT + n0;
        __half2 p01 = __floats2half2_rn(acc[i][0], acc[i][1]);
        __half2 p23 = __floats2half2_rn(acc[i][2], acc[i][3]);
        uint2 hv;
        hv.x = *reinterpret_cast<uint32_t*>(&p01);
        hv.y = *reinterpret_cast<uint32_t*>(&p23);
        *reinterpret_cast<uint2*>(&h16[idx]) = hv;
    }
    // s,t epilogue: each warp owns rows m0..m0+7 fully (cols across lanes)
    float4 a1v = *(const float4*)&a[n0];
    float4 a2v = *(const float4*)&a[F_OUT + n0];
#pragma unroll
    for (int i = 0; i < 8; i++) {
        float ss = acc[i][0] * a1v.x + acc[i][1] * a1v.y +
                   acc[i][2] * a1v.z + acc[i][3] * a1v.w;
        float tt = acc[i][0] * a2v.x + acc[i][1] * a2v.y +
                   acc[i][2] * a2v.z + acc[i][3] * a2v.w;
#pragma unroll
        for (int off = 16; off > 0; off >>= 1) {
            ss += __shfl_xor_sync(0xffffffffu, ss, off);
            tt += __shfl_xor_sync(0xffffffffu, tt, off);
        }
        if (tx == 0) { s[rowBase + m0 + i] = ss; t[rowBase + m0 + i] = tt; }
    }
}

// ---------------- kernel 2: E1 = exp(t-4), E2 = exp(0.2t-4) ----------------
__global__ void __launch_bounds__(256) k_prep(const float* __restrict__ t,
                                              float* __restrict__ E1,
                                              float* __restrict__ E2) {
    int j = blockIdx.x * 256 + threadIdx.x;
    float tj = t[j];
    E1[j] = __expf(tj - 4.0f);
    E2[j] = __expf(0.2f * tj - 4.0f);
}

// ---------------- kernel 3: fused P-compute + P@H (HMMA) + Z ---------------
// grid = 128: (bid>>1) = M-block of 128 rows, (bid&1) = K half (4096 nodes).
// P~_ij = exp(lrelu(s_i+t_j) - 8) = max(F1_i*E1_j, F2_i*E2_j)  (no inner exp)
// Double-buffered SMEM; fill of chunk c+1 overlaps MMA of chunk c.
#define BK     64
#define NCHUNK (4096 / BK)
#define PS_STRIDE 72     // fp16 elems per row (64 + 8 pad)
#define HS_STRIDE 136    // fp16 elems per row (128 + 8 pad)
#define PS_BUF (128 * PS_STRIDE)
#define HS_BUF (BK * HS_STRIDE)
#define SMEM_AV ((2 * PS_BUF + 2 * HS_BUF) * 2)

__global__ void __launch_bounds__(256, 1) k_av_mma(const int* __restrict__ adj,
                                                   const __half* __restrict__ h16,
                                                   const float* __restrict__ s,
                                                   const float* __restrict__ E1,
                                                   const float* __restrict__ E2,
                                                   float* __restrict__ part,
                                                   float* __restrict__ zp) {
    extern __shared__ char smem[];
    __half* Ps = (__half*)smem;                       // [2][PS_BUF]
    __half* Hs = (__half*)(smem + 2 * PS_BUF * 2);    // [2][HS_BUF]

    const int tid  = threadIdx.x;
    const int wid  = tid >> 5;
    const int lane = tid & 31;
    const int rowBase = (blockIdx.x >> 1) * 128;
    const int kh      = blockIdx.x & 1;
    const int jBase   = kh * 4096;

    // P-fill mapping: thread owns row (tid>>1), col half (tid&1)*32
    const int prow  = tid >> 1;
    const int chalf = (tid & 1) * 32;
    const float sR  = s[rowBase + prow];
    const float F1  = __expf(sR - 4.0f);
    const float F2  = __expf(0.2f * sR - 4.0f);
    const int4* arow = (const int4*)(adj + (size_t)(rowBase + prow) * N_NODES);

    const uint32_t psBase = (uint32_t)__cvta_generic_to_shared(Ps);
    const uint32_t hsBase = (uint32_t)__cvta_generic_to_shared(Hs);
    const uint32_t aAddr0 = psBase + (uint32_t)((wid * 16 + (lane & 15)) * (PS_STRIDE * 2))
                                   + (uint32_t)((lane >> 4) * 16);

    float acc[16][4];
#pragma unroll
    for (int i = 0; i < 16; i++)
#pragma unroll
        for (int j = 0; j < 4; j++) acc[i][j] = 0.f;
    float z = 0.f;

    // ---- fill helpers (inlined via lambdas) ----
    auto fillP = [&](int c, int buf) {
        const int j0 = jBase + c * BK;
        const int4* ap = arow + (j0 + chalf) / 4;
        __half* pr = Ps + buf * PS_BUF + prow * PS_STRIDE + chalf;
#pragma unroll
        for (int q = 0; q < 8; q++) {
            int4   av  = ap[q];
            float4 e1v = *(const float4*)&E1[j0 + chalf + q * 4];
            float4 e2v = *(const float4*)&E2[j0 + chalf + q * 4];
            float p0 = fmaxf(F1 * e1v.x, F2 * e2v.x);
            float p1 = fmaxf(F1 * e1v.y, F2 * e2v.y);
            float p2 = fmaxf(F1 * e1v.z, F2 * e2v.z);
            float p3 = fmaxf(F1 * e1v.w, F2 * e2v.w);
            p0 = (av.x > 0) ? p0 : 0.f;
            p1 = (av.y > 0) ? p1 : 0.f;
            p2 = (av.z > 0) ? p2 : 0.f;
            p3 = (av.w > 0) ? p3 : 0.f;
            z += (p0 + p1) + (p2 + p3);
            __half2 h01 = __floats2half2_rn(p0, p1);
            __half2 h23 = __floats2half2_rn(p2, p3);
            uint2 stv;
            stv.x = *reinterpret_cast<uint32_t*>(&h01);
            stv.y = *reinterpret_cast<uint32_t*>(&h23);
            *reinterpret_cast<uint2*>(pr + q * 4) = stv;
        }
    };
    auto fillH = [&](int c, int buf) {
        const int j0 = jBase + c * BK;
        __half* hb = Hs + buf * HS_BUF;
#pragma unroll
        for (int i = 0; i < 4; i++) {
            int idx = tid + i * 256;
            int r = idx >> 4;
            int g = idx & 15;
            const uint4 v = *reinterpret_cast<const uint4*>(
                h16 + (size_t)(j0 + r) * F_OUT + g * 8);
            *reinterpret_cast<uint4*>(hb + r * HS_STRIDE + g * 8) = v;
        }
    };

    // prologue: chunk 0 -> buf 0
    fillP(0, 0);
    fillH(0, 0);
    __syncthreads();

    for (int c = 0; c < NCHUNK; c++) {
        const int cb = c & 1;
        // fill next chunk into the other buffer (overlaps with MMA below)
        if (c + 1 < NCHUNK) {
            fillP(c + 1, cb ^ 1);
            fillH(c + 1, cb ^ 1);
        }
        // MMA on current buffer
        const uint32_t psB = aAddr0 + (uint32_t)(cb * PS_BUF * 2);
        const uint32_t hsB = hsBase + (uint32_t)(cb * HS_BUF * 2);
#pragma unroll
        for (int kt = 0; kt < 4; kt++) {
            uint32_t afr[4];
            ldsm_x4(afr, psB + kt * 32);
            const uint32_t bRowAddr = hsB
                + (uint32_t)((kt * 16 + (lane & 15)) * (HS_STRIDE * 2))
                + (uint32_t)((lane >> 4) * 16);
#pragma unroll
            for (int np = 0; np < 8; np++) {
                uint32_t b[4];
                ldsm_x4_t(b, bRowAddr + np * 32);
                mma16816(acc[np * 2 + 0], afr, b[0], b[1]);
                mma16816(acc[np * 2 + 1], afr, b[2], b[3]);
            }
        }
        __syncthreads();
    }

    // ---- Z: combine the two column-halves of each row, store partial ----
    z += __shfl_xor_sync(0xffffffffu, z, 1);
    if ((tid & 1) == 0) zp[kh * N_NODES + rowBase + prow] = z;

    // ---- numerator partial: fragment scatter (float2 stores) ----
    float* partOut = part + (size_t)kh * N_NODES * F_OUT;
    const int r0 = rowBase + wid * 16 + (lane >> 2);
    const int c0 = (lane & 3) * 2;
#pragma unroll
    for (int nt = 0; nt < 16; nt++) {
        *(float2*)&partOut[(size_t)r0 * F_OUT + nt * 8 + c0] =
            make_float2(acc[nt][0], acc[nt][1]);
        *(float2*)&partOut[(size_t)(r0 + 8) * F_OUT + nt * 8 + c0] =
            make_float2(acc[nt][2], acc[nt][3]);
    }
}

// ---------------- kernel 4: out = (n0+n1) / (z0+z1) ------------------------
__global__ void __launch_bounds__(256) k_reduce(const float* __restrict__ part,
                                                const float* __restrict__ zp,
                                                float* __restrict__ out) {
    int i = (blockIdx.x * 256 + threadIdx.x) * 4;
    int row = i / F_OUT;
    float zinv = 1.f / (zp[row] + zp[N_NODES + row]);
    float4 a = *(const float4*)&part[i];
    float4 b = *(const float4*)&part[N_NODES * F_OUT + i];
    float4 v = make_float4((a.x + b.x) * zinv, (a.y + b.y) * zinv,
                           (a.z + b.z) * zinv, (a.w + b.w) * zinv);
    *(float4*)&out[i] = v;
}

// ---------------- launch ----------------
extern "C" void kernel_launch(void* const* d_in, const int* in_sizes, int n_in,
                              void* d_out, int out_size) {
    const float* x   = (const float*)d_in[0];
    const int*   adj = (const int*)  d_in[1];
    const float* W   = (const float*)d_in[2];
    const float* a   = (const float*)d_in[3];
    float* out = (float*)d_out;

    float *s, *t, *E1, *E2, *part, *zp;
    __half* h16;
    cudaGetSymbolAddress((void**)&h16,  g_h16);
    cudaGetSymbolAddress((void**)&s,    g_s);
    cudaGetSymbolAddress((void**)&t,    g_t);
    cudaGetSymbolAddress((void**)&E1,   g_E1);
    cudaGetSymbolAddress((void**)&E2,   g_E2);
    cudaGetSymbolAddress((void**)&part, g_part);
    cudaGetSymbolAddress((void**)&zp,   g_zp);

    cudaFuncSetAttribute(k_av_mma, cudaFuncAttributeMaxDynamicSharedMemorySize, SMEM_AV);

    k_gemm_h <<<N_NODES / GH_BM, 256>>>(x, W, a, h16, s, t);
    k_prep   <<<N_NODES / 256,   256>>>(t, E1, E2);
    k_av_mma <<<128, 256, SMEM_AV>>>(adj, h16, s, E1, E2, part, zp);
    k_reduce <<<N_NODES * F_OUT / 1024, 256>>>(part, zp, out);
}

// round 5
// speedup vs baseline: 4.4446x; 1.3556x over previous
#include <cuda_runtime.h>
#include <cuda_fp16.h>
#include <float.h>
#include <stdint.h>

#define N_NODES 8192
#define F_IN    256
#define F_OUT   128

// ---------------- scratch (allocation-free: device globals) ----------------
__device__ __half g_h16 [N_NODES * F_OUT];        // fp16 h, natural layout
__device__ float  g_s   [N_NODES];
__device__ float  g_t   [N_NODES];
__device__ float  g_E1  [N_NODES];                // exp(t - 4)
__device__ float  g_E2  [N_NODES];                // exp(0.2t - 4)
__device__ float  g_part[2 * N_NODES * F_OUT];    // K-split numerator partials
__device__ float  g_zp  [2 * N_NODES];            // K-split Z partials

// ---------------- warp-mma helpers (baseline PTX, sm_80+) -----------------
__device__ __forceinline__ void ldsm_x4(uint32_t* r, uint32_t addr) {
    asm volatile("ldmatrix.sync.aligned.m8n8.x4.shared.b16 {%0,%1,%2,%3}, [%4];"
                 : "=r"(r[0]), "=r"(r[1]), "=r"(r[2]), "=r"(r[3]) : "r"(addr));
}
__device__ __forceinline__ void ldsm_x4_t(uint32_t* r, uint32_t addr) {
    asm volatile("ldmatrix.sync.aligned.m8n8.x4.trans.shared.b16 {%0,%1,%2,%3}, [%4];"
                 : "=r"(r[0]), "=r"(r[1]), "=r"(r[2]), "=r"(r[3]) : "r"(addr));
}
__device__ __forceinline__ void mma16816(float* c, const uint32_t* a,
                                         uint32_t b0, uint32_t b1) {
    asm volatile(
        "mma.sync.aligned.m16n8k16.row.col.f32.f16.f16.f32 "
        "{%0,%1,%2,%3}, {%4,%5,%6,%7}, {%8,%9}, {%0,%1,%2,%3};"
        : "+f"(c[0]), "+f"(c[1]), "+f"(c[2]), "+f"(c[3])
        : "r"(a[0]), "r"(a[1]), "r"(a[2]), "r"(a[3]), "r"(b0), "r"(b1));
}

// ---------------- kernel 1: h16 = fp16(x@W);  s = h@a1, t = h@a2 ----------
#define GH_BM 64
#define GH_BK 16
__global__ void __launch_bounds__(256) k_gemm_h(const float* __restrict__ x,
                                                const float* __restrict__ W,
                                                const float* __restrict__ a,
                                                __half* __restrict__ h16,
                                                float* __restrict__ s,
                                                float* __restrict__ t) {
    __shared__ float As[GH_BK][GH_BM];
    __shared__ float Bs[GH_BK][F_OUT];
    const int tid = threadIdx.x;
    const int rowBase = blockIdx.x * GH_BM;
    const int tx = tid & 31;
    const int ty = tid >> 5;
    const int m0 = ty * 8;
    const int n0 = tx * 4;

    float acc[8][4];
#pragma unroll
    for (int i = 0; i < 8; i++)
#pragma unroll
        for (int j = 0; j < 4; j++) acc[i][j] = 0.f;

    for (int k0 = 0; k0 < F_IN; k0 += GH_BK) {
        {
            int r  = tid >> 2;
            int kc = (tid & 3) * 4;
            float4 v = *(const float4*)&x[(rowBase + r) * F_IN + k0 + kc];
            As[kc + 0][r] = v.x; As[kc + 1][r] = v.y;
            As[kc + 2][r] = v.z; As[kc + 3][r] = v.w;
        }
#pragma unroll
        for (int rep = 0; rep < 2; rep++) {
            int i4 = tid + rep * 256;
            int kk = i4 >> 5;
            int nn = (i4 & 31) * 4;
            *(float4*)&Bs[kk][nn] = *(const float4*)&W[(k0 + kk) * F_OUT + nn];
        }
        __syncthreads();
#pragma unroll
        for (int k = 0; k < GH_BK; k++) {
            float a_reg[8];
#pragma unroll
            for (int i = 0; i < 8; i++) a_reg[i] = As[k][m0 + i];
            float4 b = *(const float4*)&Bs[k][n0];
#pragma unroll
            for (int i = 0; i < 8; i++) {
                acc[i][0] += a_reg[i] * b.x;
                acc[i][1] += a_reg[i] * b.y;
                acc[i][2] += a_reg[i] * b.z;
                acc[i][3] += a_reg[i] * b.w;
            }
        }
        __syncthreads();
    }
    // h16 store
#pragma unroll
    for (int i = 0; i < 8; i++) {
        size_t idx = (size_t)(rowBase + m0 + i) * F_OUT + n0;
        __half2 p01 = __floats2half2_rn(acc[i][0], acc[i][1]);
        __half2 p23 = __floats2half2_rn(acc[i][2], acc[i][3]);
        uint2 hv;
        hv.x = *reinterpret_cast<uint32_t*>(&p01);
        hv.y = *reinterpret_cast<uint32_t*>(&p23);
        *reinterpret_cast<uint2*>(&h16[idx]) = hv;
    }
    // s,t epilogue
    float4 a1v = *(const float4*)&a[n0];
    float4 a2v = *(const float4*)&a[F_OUT + n0];
#pragma unroll
    for (int i = 0; i < 8; i++) {
        float ss = acc[i][0] * a1v.x + acc[i][1] * a1v.y +
                   acc[i][2] * a1v.z + acc[i][3] * a1v.w;
        float tt = acc[i][0] * a2v.x + acc[i][1] * a2v.y +
                   acc[i][2] * a2v.z + acc[i][3] * a2v.w;
#pragma unroll
        for (int off = 16; off > 0; off >>= 1) {
            ss += __shfl_xor_sync(0xffffffffu, ss, off);
            tt += __shfl_xor_sync(0xffffffffu, tt, off);
        }
        if (tx == 0) { s[rowBase + m0 + i] = ss; t[rowBase + m0 + i] = tt; }
    }
}

// ---------------- kernel 2: E1 = exp(t-4), E2 = exp(0.2t-4) ----------------
__global__ void __launch_bounds__(256) k_prep(const float* __restrict__ t,
                                              float* __restrict__ E1,
                                              float* __restrict__ E2) {
    int j = blockIdx.x * 256 + threadIdx.x;
    float tj = t[j];
    E1[j] = __expf(tj - 4.0f);
    E2[j] = __expf(0.2f * tj - 4.0f);
}

// ---------------- kernel 3: fused P-compute + P@H (HMMA) + Z ---------------
// grid = 128: (bid>>1) = M-block of 128 rows, (bid&1) = K half (4096 nodes).
// P~_ij = exp(lrelu(s_i+t_j) - 8) = max(F1_i*E1_j, F2_i*E2_j)
// COALESCED fill: pass p, warp w -> rows w*16+p*2+(lane>>4), cols (lane&15)*4.
// Warp-wide adj LDG touches 4 cache lines (vs 32 in R4).
#define BK     64
#define NCHUNK (4096 / BK)
#define PS_STRIDE 72     // fp16 elems per row (64 + 8 pad)
#define HS_STRIDE 136    // fp16 elems per row (128 + 8 pad)
#define PS_BUF (128 * PS_STRIDE)
#define HS_BUF (BK * HS_STRIDE)
#define SMEM_F  (2 * PS_BUF * 2 + 2 * HS_BUF * 2)
#define SMEM_AV (SMEM_F + 2 * 128 * 4)

__global__ void __launch_bounds__(256, 1) k_av_mma(const int* __restrict__ adj,
                                                   const __half* __restrict__ h16,
                                                   const float* __restrict__ s,
                                                   const float* __restrict__ E1,
                                                   const float* __restrict__ E2,
                                                   float* __restrict__ part,
                                                   float* __restrict__ zp) {
    extern __shared__ char smem[];
    __half* Ps  = (__half*)smem;                       // [2][PS_BUF]
    __half* Hs  = (__half*)(smem + 2 * PS_BUF * 2);    // [2][HS_BUF]
    float*  sF1 = (float*)(smem + SMEM_F);             // [128]
    float*  sF2 = sF1 + 128;

    const int tid  = threadIdx.x;
    const int wid  = tid >> 5;
    const int lane = tid & 31;
    const int rowBase = (blockIdx.x >> 1) * 128;
    const int kh      = blockIdx.x & 1;
    const int jBase   = kh * 4096;

    // per-row factors into SMEM
    if (tid < 128) {
        float sR = s[rowBase + tid];
        sF1[tid] = __expf(sR - 4.0f);
        sF2[tid] = __expf(0.2f * sR - 4.0f);
    }

    const int jc   = (lane & 15) * 4;          // column offset within chunk
    const int rsub = lane >> 4;                // 0/1: which of warp's 2 rows/pass

    const uint32_t psBase = (uint32_t)__cvta_generic_to_shared(Ps);
    const uint32_t hsBase = (uint32_t)__cvta_generic_to_shared(Hs);
    const uint32_t aAddr0 = psBase + (uint32_t)((wid * 16 + (lane & 15)) * (PS_STRIDE * 2))
                                   + (uint32_t)((lane >> 4) * 16);

    float acc[16][4];
#pragma unroll
    for (int i = 0; i < 16; i++)
#pragma unroll
        for (int j = 0; j < 4; j++) acc[i][j] = 0.f;
    float z[8];
#pragma unroll
    for (int p = 0; p < 8; p++) z[p] = 0.f;

    auto fillP = [&](int c, int buf) {
        const int j0 = jBase + c * BK;
        const float4 e1v = *(const float4*)&E1[j0 + jc];
        const float4 e2v = *(const float4*)&E2[j0 + jc];
        __half* pb = Ps + buf * PS_BUF;
#pragma unroll
        for (int p = 0; p < 8; p++) {
            const int row = wid * 16 + p * 2 + rsub;
            const int4 av = *(const int4*)&adj[(size_t)(rowBase + row) * N_NODES + j0 + jc];
            const float f1 = sF1[row];
            const float f2 = sF2[row];
            float p0 = fmaxf(f1 * e1v.x, f2 * e2v.x);
            float p1 = fmaxf(f1 * e1v.y, f2 * e2v.y);
            float p2 = fmaxf(f1 * e1v.z, f2 * e2v.z);
            float p3 = fmaxf(f1 * e1v.w, f2 * e2v.w);
            p0 = (av.x > 0) ? p0 : 0.f;
            p1 = (av.y > 0) ? p1 : 0.f;
            p2 = (av.z > 0) ? p2 : 0.f;
            p3 = (av.w > 0) ? p3 : 0.f;
            z[p] += (p0 + p1) + (p2 + p3);
            __half2 h01 = __floats2half2_rn(p0, p1);
            __half2 h23 = __floats2half2_rn(p2, p3);
            uint2 stv;
            stv.x = *reinterpret_cast<uint32_t*>(&h01);
            stv.y = *reinterpret_cast<uint32_t*>(&h23);
            *reinterpret_cast<uint2*>(pb + row * PS_STRIDE + jc) = stv;
        }
    };
    auto fillH = [&](int c, int buf) {
        const int j0 = jBase + c * BK;
        __half* hb = Hs + buf * HS_BUF;
#pragma unroll
        for (int i = 0; i < 4; i++) {
            int idx = tid + i * 256;
            int r = idx >> 4;
            int g = idx & 15;
            const uint4 v = *reinterpret_cast<const uint4*>(
                h16 + (size_t)(j0 + r) * F_OUT + g * 8);
            *reinterpret_cast<uint4*>(hb + r * HS_STRIDE + g * 8) = v;
        }
    };

    __syncthreads();     // sF1/sF2 ready
    fillP(0, 0);
    fillH(0, 0);
    __syncthreads();

    for (int c = 0; c < NCHUNK; c++) {
        const int cb = c & 1;
        if (c + 1 < NCHUNK) {
            fillP(c + 1, cb ^ 1);
            fillH(c + 1, cb ^ 1);
        }
        const uint32_t psB = aAddr0 + (uint32_t)(cb * PS_BUF * 2);
        const uint32_t hsB = hsBase + (uint32_t)(cb * HS_BUF * 2);
#pragma unroll
        for (int kt = 0; kt < 4; kt++) {
            uint32_t afr[4];
            ldsm_x4(afr, psB + kt * 32);
            const uint32_t bRowAddr = hsB
                + (uint32_t)((kt * 16 + (lane & 15)) * (HS_STRIDE * 2))
                + (uint32_t)((lane >> 4) * 16);
#pragma unroll
            for (int np = 0; np < 8; np++) {
                uint32_t b[4];
                ldsm_x4_t(b, bRowAddr + np * 32);
                mma16816(acc[np * 2 + 0], afr, b[0], b[1]);
                mma16816(acc[np * 2 + 1], afr, b[2], b[3]);
            }
        }
        __syncthreads();
    }

    // ---- Z: reduce each z[p] across its 16-lane group ----
#pragma unroll
    for (int p = 0; p < 8; p++) {
        float zz = z[p];
        zz += __shfl_xor_sync(0xffffffffu, zz, 1);
        zz += __shfl_xor_sync(0xffffffffu, zz, 2);
        zz += __shfl_xor_sync(0xffffffffu, zz, 4);
        zz += __shfl_xor_sync(0xffffffffu, zz, 8);
        if ((lane & 15) == 0)
            zp[kh * N_NODES + rowBase + wid * 16 + p * 2 + rsub] = zz;
    }

    // ---- numerator partial: fragment scatter (float2 stores) ----
    float* partOut = part + (size_t)kh * N_NODES * F_OUT;
    const int r0 = rowBase + wid * 16 + (lane >> 2);
    const int c0 = (lane & 3) * 2;
#pragma unroll
    for (int nt = 0; nt < 16; nt++) {
        *(float2*)&partOut[(size_t)r0 * F_OUT + nt * 8 + c0] =
            make_float2(acc[nt][0], acc[nt][1]);
        *(float2*)&partOut[(size_t)(r0 + 8) * F_OUT + nt * 8 + c0] =
            make_float2(acc[nt][2], acc[nt][3]);
    }
}

// ---------------- kernel 4: out = (n0+n1) / (z0+z1) ------------------------
__global__ void __launch_bounds__(256) k_reduce(const float* __restrict__ part,
                                                const float* __restrict__ zp,
                                                float* __restrict__ out) {
    int i = (blockIdx.x * 256 + threadIdx.x) * 4;
    int row = i / F_OUT;
    float zinv = 1.f / (zp[row] + zp[N_NODES + row]);
    float4 a = *(const float4*)&part[i];
    float4 b = *(const float4*)&part[N_NODES * F_OUT + i];
    float4 v = make_float4((a.x + b.x) * zinv, (a.y + b.y) * zinv,
                           (a.z + b.z) * zinv, (a.w + b.w) * zinv);
    *(float4*)&out[i] = v;
}

// ---------------- launch ----------------
extern "C" void kernel_launch(void* const* d_in, const int* in_sizes, int n_in,
                              void* d_out, int out_size) {
    const float* x   = (const float*)d_in[0];
    const int*   adj = (const int*)  d_in[1];
    const float* W   = (const float*)d_in[2];
    const float* a   = (const float*)d_in[3];
    float* out = (float*)d_out;

    float *s, *t, *E1, *E2, *part, *zp;
    __half* h16;
    cudaGetSymbolAddress((void**)&h16,  g_h16);
    cudaGetSymbolAddress((void**)&s,    g_s);
    cudaGetSymbolAddress((void**)&t,    g_t);
    cudaGetSymbolAddress((void**)&E1,   g_E1);
    cudaGetSymbolAddress((void**)&E2,   g_E2);
    cudaGetSymbolAddress((void**)&part, g_part);
    cudaGetSymbolAddress((void**)&zp,   g_zp);

    cudaFuncSetAttribute(k_av_mma, cudaFuncAttributeMaxDynamicSharedMemorySize, SMEM_AV);

    k_gemm_h <<<N_NODES / GH_BM, 256>>>(x, W, a, h16, s, t);
    k_prep   <<<N_NODES / 256,   256>>>(t, E1, E2);
    k_av_mma <<<128, 256, SMEM_AV>>>(adj, h16, s, E1, E2, part, zp);
    k_reduce <<<N_NODES * F_OUT / 1024, 256>>>(part, zp, out);
}

// round 7
// speedup vs baseline: 4.7268x; 1.0635x over previous
#include <cuda_runtime.h>
#include <cuda_fp16.h>
#include <float.h>
#include <stdint.h>

#define N_NODES 8192
#define F_IN    256
#define F_OUT   128
#define KSPLIT  4

// ---------------- scratch (allocation-free: device globals) ----------------
__device__ __half g_h16 [N_NODES * F_OUT];          // fp16 h, natural layout
__device__ float  g_F1  [N_NODES];                  // exp(s - 4)
__device__ float  g_F2  [N_NODES];                  // exp(0.2s - 4)
__device__ float  g_E1  [N_NODES];                  // exp(t - 4)
__device__ float  g_E2  [N_NODES];                  // exp(0.2t - 4)
__device__ float  g_part[KSPLIT * N_NODES * F_OUT]; // K-split numerator partials
__device__ float  g_zp  [KSPLIT * N_NODES];         // K-split Z partials

// ---------------- warp-mma helpers (baseline PTX, sm_80+) -----------------
__device__ __forceinline__ void ldsm_x4(uint32_t* r, uint32_t addr) {
    asm volatile("ldmatrix.sync.aligned.m8n8.x4.shared.b16 {%0,%1,%2,%3}, [%4];"
                 : "=r"(r[0]), "=r"(r[1]), "=r"(r[2]), "=r"(r[3]) : "r"(addr));
}
__device__ __forceinline__ void ldsm_x4_t(uint32_t* r, uint32_t addr) {
    asm volatile("ldmatrix.sync.aligned.m8n8.x4.trans.shared.b16 {%0,%1,%2,%3}, [%4];"
                 : "=r"(r[0]), "=r"(r[1]), "=r"(r[2]), "=r"(r[3]) : "r"(addr));
}
__device__ __forceinline__ void mma16816(float* c, const uint32_t* a,
                                         uint32_t b0, uint32_t b1) {
    asm volatile(
        "mma.sync.aligned.m16n8k16.row.col.f32.f16.f16.f32 "
        "{%0,%1,%2,%3}, {%4,%5,%6,%7}, {%8,%9}, {%0,%1,%2,%3};"
        : "+f"(c[0]), "+f"(c[1]), "+f"(c[2]), "+f"(c[3])
        : "r"(a[0]), "r"(a[1]), "r"(a[2]), "r"(a[3]), "r"(b0), "r"(b1));
}

// -------- kernel 1: h16 = fp16(x@W); F1,F2,E1,E2 from s,t in epilogue ------
#define GH_BM 64
#define GH_BK 16
__global__ void __launch_bounds__(256) k_gemm_h(const float* __restrict__ x,
                                                const float* __restrict__ W,
                                                const float* __restrict__ a,
                                                __half* __restrict__ h16,
                                                float* __restrict__ F1,
                                                float* __restrict__ F2,
                                                float* __restrict__ E1,
                                                float* __restrict__ E2) {
    __shared__ float As[GH_BK][GH_BM];
    __shared__ float Bs[GH_BK][F_OUT];
    const int tid = threadIdx.x;
    const int rowBase = blockIdx.x * GH_BM;
    const int tx = tid & 31;
    const int ty = tid >> 5;
    const int m0 = ty * 8;
    const int n0 = tx * 4;

    float acc[8][4];
#pragma unroll
    for (int i = 0; i < 8; i++)
#pragma unroll
        for (int j = 0; j < 4; j++) acc[i][j] = 0.f;

    for (int k0 = 0; k0 < F_IN; k0 += GH_BK) {
        {
            int r  = tid >> 2;
            int kc = (tid & 3) * 4;
            float4 v = *(const float4*)&x[(rowBase + r) * F_IN + k0 + kc];
            As[kc + 0][r] = v.x; As[kc + 1][r] = v.y;
            As[kc + 2][r] = v.z; As[kc + 3][r] = v.w;
        }
#pragma unroll
        for (int rep = 0; rep < 2; rep++) {
            int i4 = tid + rep * 256;
            int kk = i4 >> 5;
            int nn = (i4 & 31) * 4;
            *(float4*)&Bs[kk][nn] = *(const float4*)&W[(k0 + kk) * F_OUT + nn];
        }
        __syncthreads();
#pragma unroll
        for (int k = 0; k < GH_BK; k++) {
            float a_reg[8];
#pragma unroll
            for (int i = 0; i < 8; i++) a_reg[i] = As[k][m0 + i];
            float4 b = *(const float4*)&Bs[k][n0];
#pragma unroll
            for (int i = 0; i < 8; i++) {
                acc[i][0] += a_reg[i] * b.x;
                acc[i][1] += a_reg[i] * b.y;
                acc[i][2] += a_reg[i] * b.z;
                acc[i][3] += a_reg[i] * b.w;
            }
        }
        __syncthreads();
    }
    // h16 store
#pragma unroll
    for (int i = 0; i < 8; i++) {
        size_t idx = (size_t)(rowBase + m0 + i) * F_OUT + n0;
        __half2 p01 = __floats2half2_rn(acc[i][0], acc[i][1]);
        __half2 p23 = __floats2half2_rn(acc[i][2], acc[i][3]);
        uint2 hv;
        hv.x = *reinterpret_cast<uint32_t*>(&p01);
        hv.y = *reinterpret_cast<uint32_t*>(&p23);
        *reinterpret_cast<uint2*>(&h16[idx]) = hv;
    }
    // s,t + exp-factor epilogue
    float4 a1v = *(const float4*)&a[n0];
    float4 a2v = *(const float4*)&a[F_OUT + n0];
#pragma unroll
    for (int i = 0; i < 8; i++) {
        float ss = acc[i][0] * a1v.x + acc[i][1] * a1v.y +
                   acc[i][2] * a1v.z + acc[i][3] * a1v.w;
        float tt = acc[i][0] * a2v.x + acc[i][1] * a2v.y +
                   acc[i][2] * a2v.z + acc[i][3] * a2v.w;
#pragma unroll
        for (int off = 16; off > 0; off >>= 1) {
            ss += __shfl_xor_sync(0xffffffffu, ss, off);
            tt += __shfl_xor_sync(0xffffffffu, tt, off);
        }
        if (tx == 0) {
            int r = rowBase + m0 + i;
            F1[r] = __expf(ss - 4.0f);
            F2[r] = __expf(0.2f * ss - 4.0f);
            E1[r] = __expf(tt - 4.0f);
            E2[r] = __expf(0.2f * tt - 4.0f);
        }
    }
}

// ---------------- kernel 2: fused P-compute + P@H (HMMA) + Z ---------------
// grid = 256: (bid>>2) = M-block of 128 rows, (bid&3) = K quarter (2048 cols).
// P~_ij = exp(lrelu(s_i+t_j) - 8) = max(F1_i*E1_j, F2_i*E2_j)
// Coalesced fill; double-buffered SMEM; 2 CTAs/SM for latency hiding.
#define BK     64
#define KCOLS  (N_NODES / KSPLIT)     // 2048
#define NCHUNK (KCOLS / BK)           // 32
#define PS_STRIDE 72
#define HS_STRIDE 136
#define PS_BUF (128 * PS_STRIDE)
#define HS_BUF (BK * HS_STRIDE)
#define SMEM_F  (2 * PS_BUF * 2 + 2 * HS_BUF * 2)
#define SMEM_AV (SMEM_F + 2 * 128 * 4)

__global__ void __launch_bounds__(256, 2) k_av_mma(const int* __restrict__ adj,
                                                   const __half* __restrict__ h16,
                                                   const float* __restrict__ F1,
                                                   const float* __restrict__ F2,
                                                   const float* __restrict__ E1,
                                                   const float* __restrict__ E2,
                                                   float* __restrict__ part,
                                                   float* __restrict__ zp) {
    extern __shared__ char smem[];
    __half* Ps  = (__half*)smem;                       // [2][PS_BUF]
    __half* Hs  = (__half*)(smem + 2 * PS_BUF * 2);    // [2][HS_BUF]
    float*  sF1 = (float*)(smem + SMEM_F);             // [128]
    float*  sF2 = sF1 + 128;

    const int tid  = threadIdx.x;
    const int wid  = tid >> 5;
    const int lane = tid & 31;
    const int rowBase = (blockIdx.x >> 2) * 128;
    const int kh      = blockIdx.x & 3;
    const int jBase   = kh * KCOLS;

    if (tid < 128) {
        sF1[tid] = F1[rowBase + tid];
        sF2[tid] = F2[rowBase + tid];
    }

    const int jc   = (lane & 15) * 4;
    const int rsub = lane >> 4;

    const uint32_t psBase = (uint32_t)__cvta_generic_to_shared(Ps);
    const uint32_t hsBase = (uint32_t)__cvta_generic_to_shared(Hs);
    const uint32_t aAddr0 = psBase + (uint32_t)((wid * 16 + (lane & 15)) * (PS_STRIDE * 2))
                                   + (uint32_t)((lane >> 4) * 16);

    float acc[16][4];
#pragma unroll
    for (int i = 0; i < 16; i++)
#pragma unroll
        for (int j = 0; j < 4; j++) acc[i][j] = 0.f;
    float z[8];
#pragma unroll
    for (int p = 0; p < 8; p++) z[p] = 0.f;

    auto fillP = [&](int c, int buf) {
        const int j0 = jBase + c * BK;
        const float4 e1v = *(const float4*)&E1[j0 + jc];
        const float4 e2v = *(const float4*)&E2[j0 + jc];
        __half* pb = Ps + buf * PS_BUF;
#pragma unroll
        for (int p = 0; p < 8; p++) {
            const int row = wid * 16 + p * 2 + rsub;
            const int4 av = *(const int4*)&adj[(size_t)(rowBase + row) * N_NODES + j0 + jc];
            const float f1 = sF1[row];
            const float f2 = sF2[row];
            float p0 = fmaxf(f1 * e1v.x, f2 * e2v.x);
            float p1 = fmaxf(f1 * e1v.y, f2 * e2v.y);
            float p2 = fmaxf(f1 * e1v.z, f2 * e2v.z);
            float p3 = fmaxf(f1 * e1v.w, f2 * e2v.w);
            p0 = (av.x > 0) ? p0 : 0.f;
            p1 = (av.y > 0) ? p1 : 0.f;
            p2 = (av.z > 0) ? p2 : 0.f;
            p3 = (av.w > 0) ? p3 : 0.f;
            z[p] += (p0 + p1) + (p2 + p3);
            __half2 h01 = __floats2half2_rn(p0, p1);
            __half2 h23 = __floats2half2_rn(p2, p3);
            uint2 stv;
            stv.x = *reinterpret_cast<uint32_t*>(&h01);
            stv.y = *reinterpret_cast<uint32_t*>(&h23);
            *reinterpret_cast<uint2*>(pb + row * PS_STRIDE + jc) = stv;
        }
    };
    auto fillH = [&](int c, int buf) {
        const int j0 = jBase + c * BK;
        __half* hb = Hs + buf * HS_BUF;
#pragma unroll
        for (int i = 0; i < 4; i++) {
            int idx = tid + i * 256;
            int r = idx >> 4;
            int g = idx & 15;
            const uint4 v = *reinterpret_cast<const uint4*>(
                h16 + (size_t)(j0 + r) * F_OUT + g * 8);
            *reinterpret_cast<uint4*>(hb + r * HS_STRIDE + g * 8) = v;
        }
    };

    __syncthreads();
    fillP(0, 0);
    fillH(0, 0);
    __syncthreads();

    for (int c = 0; c < NCHUNK; c++) {
        const int cb = c & 1;
        if (c + 1 < NCHUNK) {
            fillP(c + 1, cb ^ 1);
            fillH(c + 1, cb ^ 1);
        }
        const uint32_t psB = aAddr0 + (uint32_t)(cb * PS_BUF * 2);
        const uint32_t hsB = hsBase + (uint32_t)(cb * HS_BUF * 2);
#pragma unroll
        for (int kt = 0; kt < 4; kt++) {
            uint32_t afr[4];
            ldsm_x4(afr, psB + kt * 32);
            const uint32_t bRowAddr = hsB
                + (uint32_t)((kt * 16 + (lane & 15)) * (HS_STRIDE * 2))
                + (uint32_t)((lane >> 4) * 16);
#pragma unroll
            for (int np = 0; np < 8; np++) {
                uint32_t b[4];
                ldsm_x4_t(b, bRowAddr + np * 32);
                mma16816(acc[np * 2 + 0], afr, b[0], b[1]);
                mma16816(acc[np * 2 + 1], afr, b[2], b[3]);
            }
        }
        __syncthreads();
    }

    // ---- Z partials ----
#pragma unroll
    for (int p = 0; p < 8; p++) {
        float zz = z[p];
        zz += __shfl_xor_sync(0xffffffffu, zz, 1);
        zz += __shfl_xor_sync(0xffffffffu, zz, 2);
        zz += __shfl_xor_sync(0xffffffffu, zz, 4);
        zz += __shfl_xor_sync(0xffffffffu, zz, 8);
        if ((lane & 15) == 0)
            zp[kh * N_NODES + rowBase + wid * 16 + p * 2 + rsub] = zz;
    }

    // ---- numerator partials ----
    float* partOut = part + (size_t)kh * N_NODES * F_OUT;
    const int r0 = rowBase + wid * 16 + (lane >> 2);
    const int c0 = (lane & 3) * 2;
#pragma unroll
    for (int nt = 0; nt < 16; nt++) {
        *(float2*)&partOut[(size_t)r0 * F_OUT + nt * 8 + c0] =
            make_float2(acc[nt][0], acc[nt][1]);
        *(float2*)&partOut[(size_t)(r0 + 8) * F_OUT + nt * 8 + c0] =
            make_float2(acc[nt][2], acc[nt][3]);
    }
}

// ---------------- kernel 3: out = sum(parts) / sum(z) ----------------------
__global__ void __launch_bounds__(256) k_reduce(const float* __restrict__ part,
                                                const float* __restrict__ zp,
                                                float* __restrict__ out) {
    int i = (blockIdx.x * 256 + threadIdx.x) * 4;
    int row = i / F_OUT;
    float zs = 0.f;
#pragma unroll
    for (int q = 0; q < KSPLIT; q++) zs += zp[q * N_NODES + row];
    float zinv = 1.f / zs;
    float4 acc = *(const float4*)&part[i];
#pragma unroll
    for (int q = 1; q < KSPLIT; q++) {
        float4 b = *(const float4*)&part[(size_t)q * N_NODES * F_OUT + i];
        acc.x += b.x; acc.y += b.y; acc.z += b.z; acc.w += b.w;
    }
    float4 v = make_float4(acc.x * zinv, acc.y * zinv, acc.z * zinv, acc.w * zinv);
    *(float4*)&out[i] = v;
}

// ---------------- launch ----------------
extern "C" void kernel_launch(void* const* d_in, const int* in_sizes, int n_in,
                              void* d_out, int out_size) {
    const float* x   = (const float*)d_in[0];
    const int*   adj = (const int*)  d_in[1];
    const float* W   = (const float*)d_in[2];
    const float* a   = (const float*)d_in[3];
    float* out = (float*)d_out;

    float *F1, *F2, *E1, *E2, *part, *zp;
    __half* h16;
    cudaGetSymbolAddress((void**)&h16,  g_h16);
    cudaGetSymbolAddress((void**)&F1,   g_F1);
    cudaGetSymbolAddress((void**)&F2,   g_F2);
    cudaGetSymbolAddress((void**)&E1,   g_E1);
    cudaGetSymbolAddress((void**)&E2,   g_E2);
    cudaGetSymbolAddress((void**)&part, g_part);
    cudaGetSymbolAddress((void**)&zp,   g_zp);

    cudaFuncSetAttribute(k_av_mma, cudaFuncAttributeMaxDynamicSharedMemorySize, SMEM_AV);

    k_gemm_h <<<N_NODES / GH_BM, 256>>>(x, W, a, h16, F1, F2, E1, E2);
    k_av_mma <<<(N_NODES / 128) * KSPLIT, 256, SMEM_AV>>>(adj, h16, F1, F2, E1, E2, part, zp);
    k_reduce <<<N_NODES * F_OUT / 1024, 256>>>(part, zp, out);
}

// round 8
// speedup vs baseline: 6.7058x; 1.4187x over previous
#include <cuda_runtime.h>
#include <cuda_fp16.h>
#include <float.h>
#include <stdint.h>

#define N_NODES 8192
#define F_IN    256
#define F_OUT   128
#define KSPLIT  4

// ---------------- scratch (allocation-free: device globals) ----------------
__device__ __half g_h16 [N_NODES * F_OUT];
__device__ float  g_F1  [N_NODES];
__device__ float  g_F2  [N_NODES];
__device__ float  g_E1  [N_NODES];
__device__ float  g_E2  [N_NODES];
__device__ float  g_part[KSPLIT * N_NODES * F_OUT];
__device__ float  g_zp  [KSPLIT * N_NODES];

// ---------------- PTX helpers (baseline, sm_80+) ---------------------------
__device__ __forceinline__ void ldsm_x4(uint32_t* r, uint32_t addr) {
    asm volatile("ldmatrix.sync.aligned.m8n8.x4.shared.b16 {%0,%1,%2,%3}, [%4];"
                 : "=r"(r[0]), "=r"(r[1]), "=r"(r[2]), "=r"(r[3]) : "r"(addr));
}
__device__ __forceinline__ void ldsm_x4_t(uint32_t* r, uint32_t addr) {
    asm volatile("ldmatrix.sync.aligned.m8n8.x4.trans.shared.b16 {%0,%1,%2,%3}, [%4];"
                 : "=r"(r[0]), "=r"(r[1]), "=r"(r[2]), "=r"(r[3]) : "r"(addr));
}
__device__ __forceinline__ void mma16816(float* c, const uint32_t* a,
                                         uint32_t b0, uint32_t b1) {
    asm volatile(
        "mma.sync.aligned.m16n8k16.row.col.f32.f16.f16.f32 "
        "{%0,%1,%2,%3}, {%4,%5,%6,%7}, {%8,%9}, {%0,%1,%2,%3};"
        : "+f"(c[0]), "+f"(c[1]), "+f"(c[2]), "+f"(c[3])
        : "r"(a[0]), "r"(a[1]), "r"(a[2]), "r"(a[3]), "r"(b0), "r"(b1));
}
__device__ __forceinline__ void cp_async16(uint32_t dst, const void* src) {
    asm volatile("cp.async.cg.shared.global [%0], [%1], 16;" :: "r"(dst), "l"(src));
}
#define CP_COMMIT() asm volatile("cp.async.commit_group;" ::: "memory")
#define CP_WAIT0()  asm volatile("cp.async.wait_group 0;" ::: "memory")

// -------- kernel 1: h16 = fp16(x@W); F1,F2,E1,E2 in epilogue (BM=32) -------
#define GH_BM 32
#define GH_BK 16
__global__ void __launch_bounds__(256, 2) k_gemm_h(const float* __restrict__ x,
                                                   const float* __restrict__ W,
                                                   const float* __restrict__ a,
                                                   __half* __restrict__ h16,
                                                   float* __restrict__ F1,
                                                   float* __restrict__ F2,
                                                   float* __restrict__ E1,
                                                   float* __restrict__ E2) {
    __shared__ float As[GH_BK][GH_BM];
    __shared__ float Bs[GH_BK][F_OUT];
    const int tid = threadIdx.x;
    const int rowBase = blockIdx.x * GH_BM;
    const int tx = tid & 31;
    const int ty = tid >> 5;
    const int m0 = ty * 4;
    const int n0 = tx * 4;

    float acc[4][4];
#pragma unroll
    for (int i = 0; i < 4; i++)
#pragma unroll
        for (int j = 0; j < 4; j++) acc[i][j] = 0.f;

    for (int k0 = 0; k0 < F_IN; k0 += GH_BK) {
        if (tid < 128) {
            int r  = tid >> 2;
            int kc = (tid & 3) * 4;
            float4 v = *(const float4*)&x[(rowBase + r) * F_IN + k0 + kc];
            As[kc + 0][r] = v.x; As[kc + 1][r] = v.y;
            As[kc + 2][r] = v.z; As[kc + 3][r] = v.w;
        }
#pragma unroll
        for (int rep = 0; rep < 2; rep++) {
            int i4 = tid + rep * 256;
            int kk = i4 >> 5;
            int nn = (i4 & 31) * 4;
            *(float4*)&Bs[kk][nn] = *(const float4*)&W[(k0 + kk) * F_OUT + nn];
        }
        __syncthreads();
#pragma unroll
        for (int k = 0; k < GH_BK; k++) {
            float a_reg[4];
#pragma unroll
            for (int i = 0; i < 4; i++) a_reg[i] = As[k][m0 + i];
            float4 b = *(const float4*)&Bs[k][n0];
#pragma unroll
            for (int i = 0; i < 4; i++) {
                acc[i][0] += a_reg[i] * b.x;
                acc[i][1] += a_reg[i] * b.y;
                acc[i][2] += a_reg[i] * b.z;
                acc[i][3] += a_reg[i] * b.w;
            }
        }
        __syncthreads();
    }
#pragma unroll
    for (int i = 0; i < 4; i++) {
        size_t idx = (size_t)(rowBase + m0 + i) * F_OUT + n0;
        __half2 p01 = __floats2half2_rn(acc[i][0], acc[i][1]);
        __half2 p23 = __floats2half2_rn(acc[i][2], acc[i][3]);
        uint2 hv;
        hv.x = *reinterpret_cast<uint32_t*>(&p01);
        hv.y = *reinterpret_cast<uint32_t*>(&p23);
        *reinterpret_cast<uint2*>(&h16[idx]) = hv;
    }
    float4 a1v = *(const float4*)&a[n0];
    float4 a2v = *(const float4*)&a[F_OUT + n0];
#pragma unroll
    for (int i = 0; i < 4; i++) {
        float ss = acc[i][0] * a1v.x + acc[i][1] * a1v.y +
                   acc[i][2] * a1v.z + acc[i][3] * a1v.w;
        float tt = acc[i][0] * a2v.x + acc[i][1] * a2v.y +
                   acc[i][2] * a2v.z + acc[i][3] * a2v.w;
#pragma unroll
        for (int off = 16; off > 0; off >>= 1) {
            ss += __shfl_xor_sync(0xffffffffu, ss, off);
            tt += __shfl_xor_sync(0xffffffffu, tt, off);
        }
        if (tx == 0) {
            int r = rowBase + m0 + i;
            F1[r] = __expf(ss - 4.0f);
            F2[r] = __expf(0.2f * ss - 4.0f);
            E1[r] = __expf(tt - 4.0f);
            E2[r] = __expf(0.2f * tt - 4.0f);
        }
    }
}

// ---------------- kernel 2: fused P-compute + P@H (HMMA) + Z ---------------
// grid = 256: (bid>>2) = M-block of 128 rows, (bid&3) = K quarter.
// Pipelined: LDG(adj,c+1)->regs & cp.async(H,c+1) issued BEFORE MMA(c);
// convert/STS after MMA blocks, so DRAM latency hides behind tensor work.
#define BK     64
#define KCOLS  (N_NODES / KSPLIT)
#define NCHUNK (KCOLS / BK)
#define PS_STRIDE 72
#define HS_STRIDE 136
#define PS_BUF (128 * PS_STRIDE)
#define HS_BUF (BK * HS_STRIDE)
#define SMEM_F  (2 * PS_BUF * 2 + 2 * HS_BUF * 2)
#define SMEM_AV (SMEM_F + 2 * 128 * 4)

__global__ void __launch_bounds__(256, 2) k_av_mma(const int* __restrict__ adj,
                                                   const __half* __restrict__ h16,
                                                   const float* __restrict__ F1,
                                                   const float* __restrict__ F2,
                                                   const float* __restrict__ E1,
                                                   const float* __restrict__ E2,
                                                   float* __restrict__ part,
                                                   float* __restrict__ zp) {
    extern __shared__ char smem[];
    __half* Ps  = (__half*)smem;
    __half* Hs  = (__half*)(smem + 2 * PS_BUF * 2);
    float*  sF1 = (float*)(smem + SMEM_F);
    float*  sF2 = sF1 + 128;

    const int tid  = threadIdx.x;
    const int wid  = tid >> 5;
    const int lane = tid & 31;
    const int rowBase = (blockIdx.x >> 2) * 128;
    const int kh      = blockIdx.x & 3;
    const int jBase   = kh * KCOLS;

    if (tid < 128) {
        sF1[tid] = F1[rowBase + tid];
        sF2[tid] = F2[rowBase + tid];
    }

    const int jc   = (lane & 15) * 4;
    const int rsub = lane >> 4;

    const uint32_t psBase = (uint32_t)__cvta_generic_to_shared(Ps);
    const uint32_t hsBase = (uint32_t)__cvta_generic_to_shared(Hs);
    const uint32_t aAddr0 = psBase + (uint32_t)((wid * 16 + (lane & 15)) * (PS_STRIDE * 2))
                                   + (uint32_t)((lane >> 4) * 16);

    float acc[16][4];
#pragma unroll
    for (int i = 0; i < 16; i++)
#pragma unroll
        for (int j = 0; j < 4; j++) acc[i][j] = 0.f;
    float z[8];
#pragma unroll
    for (int p = 0; p < 8; p++) z[p] = 0.f;

    // ---- batched adj LDG into registers (4 passes) ----
    auto ldA4 = [&](int4* av, int pbase, int c) {
        const int j0 = jBase + c * BK;
#pragma unroll
        for (int p = 0; p < 4; p++) {
            const int row = wid * 16 + (pbase + p) * 2 + rsub;
            av[p] = *(const int4*)&adj[(size_t)(rowBase + row) * N_NODES + j0 + jc];
        }
    };
    // ---- convert + STS for a 4-pass batch ----
    auto convP4 = [&](const int4* av, int pbase, int buf,
                      float4 e1v, float4 e2v) {
        __half* pb = Ps + buf * PS_BUF;
#pragma unroll
        for (int p = 0; p < 4; p++) {
            const int row = wid * 16 + (pbase + p) * 2 + rsub;
            const float f1 = sF1[row];
            const float f2 = sF2[row];
            float p0 = fmaxf(f1 * e1v.x, f2 * e2v.x);
            float p1 = fmaxf(f1 * e1v.y, f2 * e2v.y);
            float p2 = fmaxf(f1 * e1v.z, f2 * e2v.z);
            float p3 = fmaxf(f1 * e1v.w, f2 * e2v.w);
            p0 = (av[p].x > 0) ? p0 : 0.f;
            p1 = (av[p].y > 0) ? p1 : 0.f;
            p2 = (av[p].z > 0) ? p2 : 0.f;
            p3 = (av[p].w > 0) ? p3 : 0.f;
            z[pbase + p] += (p0 + p1) + (p2 + p3);
            __half2 h01 = __floats2half2_rn(p0, p1);
            __half2 h23 = __floats2half2_rn(p2, p3);
            uint2 stv;
            stv.x = *reinterpret_cast<uint32_t*>(&h01);
            stv.y = *reinterpret_cast<uint32_t*>(&h23);
            *reinterpret_cast<uint2*>(pb + row * PS_STRIDE + jc) = stv;
        }
    };
    // ---- async H fill (no registers, no scoreboard on MMA path) ----
    auto fillH_async = [&](int c, int buf) {
        const int j0 = jBase + c * BK;
        const uint32_t hb = hsBase + (uint32_t)(buf * HS_BUF * 2);
#pragma unroll
        for (int i = 0; i < 4; i++) {
            int idx = tid + i * 256;
            int r = idx >> 4;
            int g = idx & 15;
            cp_async16(hb + (uint32_t)(r * (HS_STRIDE * 2) + g * 16),
                       (const char*)(h16 + (size_t)(j0 + r) * F_OUT) + g * 16);
        }
    };
    // ---- MMA for kt pair ----
    auto mma2 = [&](int ktBase, int buf) {
        const uint32_t psB = aAddr0 + (uint32_t)(buf * PS_BUF * 2);
        const uint32_t hsB = hsBase + (uint32_t)(buf * HS_BUF * 2);
#pragma unroll
        for (int kt = ktBase; kt < ktBase + 2; kt++) {
            uint32_t afr[4];
            ldsm_x4(afr, psB + kt * 32);
            const uint32_t bRowAddr = hsB
                + (uint32_t)((kt * 16 + (lane & 15)) * (HS_STRIDE * 2))
                + (uint32_t)((lane >> 4) * 16);
#pragma unroll
            for (int np = 0; np < 8; np++) {
                uint32_t b[4];
                ldsm_x4_t(b, bRowAddr + np * 32);
                mma16816(acc[np * 2 + 0], afr, b[0], b[1]);
                mma16816(acc[np * 2 + 1], afr, b[2], b[3]);
            }
        }
    };

    __syncthreads();   // sF1/sF2 ready

    // ---- prologue: chunk 0 -> buf 0 ----
    {
        fillH_async(0, 0);
        CP_COMMIT();
        const int j0 = jBase;
        float4 e1v = *(const float4*)&E1[j0 + jc];
        float4 e2v = *(const float4*)&E2[j0 + jc];
        int4 avA[4], avB[4];
        ldA4(avA, 0, 0);
        ldA4(avB, 4, 0);
        convP4(avA, 0, 0, e1v, e2v);
        convP4(avB, 4, 0, e1v, e2v);
        CP_WAIT0();
    }
    __syncthreads();

    for (int c = 0; c < NCHUNK; c++) {
        const int cb = c & 1;
        const int nb = cb ^ 1;
        const bool pre = (c + 1 < NCHUNK);
        float4 e1n, e2n;
        int4 avA[4], avB[4];
        if (pre) {
            fillH_async(c + 1, nb);
            CP_COMMIT();
            const int j0 = jBase + (c + 1) * BK;
            e1n = *(const float4*)&E1[j0 + jc];
            e2n = *(const float4*)&E2[j0 + jc];
            ldA4(avA, 0, c + 1);
        }
        mma2(0, cb);
        if (pre) {
            convP4(avA, 0, nb, e1n, e2n);
            ldA4(avB, 4, c + 1);
        }
        mma2(2, cb);
        if (pre) {
            convP4(avB, 4, nb, e1n, e2n);
            CP_WAIT0();
        }
        __syncthreads();
    }

    // ---- Z partials ----
#pragma unroll
    for (int p = 0; p < 8; p++) {
        float zz = z[p];
        zz += __shfl_xor_sync(0xffffffffu, zz, 1);
        zz += __shfl_xor_sync(0xffffffffu, zz, 2);
        zz += __shfl_xor_sync(0xffffffffu, zz, 4);
        zz += __shfl_xor_sync(0xffffffffu, zz, 8);
        if ((lane & 15) == 0)
            zp[kh * N_NODES + rowBase + wid * 16 + p * 2 + rsub] = zz;
    }

    // ---- numerator partials ----
    float* partOut = part + (size_t)kh * N_NODES * F_OUT;
    const int r0 = rowBase + wid * 16 + (lane >> 2);
    const int c0 = (lane & 3) * 2;
#pragma unroll
    for (int nt = 0; nt < 16; nt++) {
        *(float2*)&partOut[(size_t)r0 * F_OUT + nt * 8 + c0] =
            make_float2(acc[nt][0], acc[nt][1]);
        *(float2*)&partOut[(size_t)(r0 + 8) * F_OUT + nt * 8 + c0] =
            make_float2(acc[nt][2], acc[nt][3]);
    }
}

// ---------------- kernel 3: out = sum(parts) / sum(z) ----------------------
__global__ void __launch_bounds__(256) k_reduce(const float* __restrict__ part,
                                                const float* __restrict__ zp,
                                                float* __restrict__ out) {
    int i = (blockIdx.x * 256 + threadIdx.x) * 4;
    int row = i / F_OUT;
    float zs = 0.f;
#pragma unroll
    for (int q = 0; q < KSPLIT; q++) zs += zp[q * N_NODES + row];
    float zinv = 1.f / zs;
    float4 acc = *(const float4*)&part[i];
#pragma unroll
    for (int q = 1; q < KSPLIT; q++) {
        float4 b = *(const float4*)&part[(size_t)q * N_NODES * F_OUT + i];
        acc.x += b.x; acc.y += b.y; acc.z += b.z; acc.w += b.w;
    }
    float4 v = make_float4(acc.x * zinv, acc.y * zinv, acc.z * zinv, acc.w * zinv);
    *(float4*)&out[i] = v;
}

// ---------------- launch ----------------
extern "C" void kernel_launch(void* const* d_in, const int* in_sizes, int n_in,
                              void* d_out, int out_size) {
    const float* x   = (const float*)d_in[0];
    const int*   adj = (const int*)  d_in[1];
    const float* W   = (const float*)d_in[2];
    const float* a   = (const float*)d_in[3];
    float* out = (float*)d_out;

    float *F1, *F2, *E1, *E2, *part, *zp;
    __half* h16;
    cudaGetSymbolAddress((void**)&h16,  g_h16);
    cudaGetSymbolAddress((void**)&F1,   g_F1);
    cudaGetSymbolAddress((void**)&F2,   g_F2);
    cudaGetSymbolAddress((void**)&E1,   g_E1);
    cudaGetSymbolAddress((void**)&E2,   g_E2);
    cudaGetSymbolAddress((void**)&part, g_part);
    cudaGetSymbolAddress((void**)&zp,   g_zp);

    cudaFuncSetAttribute(k_av_mma, cudaFuncAttributeMaxDynamicSharedMemorySize, SMEM_AV);

    k_gemm_h <<<N_NODES / GH_BM, 256>>>(x, W, a, h16, F1, F2, E1, E2);
    k_av_mma <<<(N_NODES / 128) * KSPLIT, 256, SMEM_AV>>>(adj, h16, F1, F2, E1, E2, part, zp);
    k_reduce <<<N_NODES * F_OUT / 1024, 256>>>(part, zp, out);
}

// round 9
// speedup vs baseline: 7.4909x; 1.1171x over previous
#include <cuda_runtime.h>
#include <cuda_fp16.h>
#include <float.h>
#include <stdint.h>

#define N_NODES 8192
#define F_IN    256
#define F_OUT   128
#define KSPLIT  4

// ---------------- scratch (allocation-free: device globals) ----------------
__device__ __half g_x16 [N_NODES * F_IN];
__device__ __half g_W16 [F_IN * F_OUT];
__device__ __half g_h16 [N_NODES * F_OUT];
__device__ float  g_F1  [N_NODES];
__device__ float  g_F2  [N_NODES];
__device__ float  g_E1  [N_NODES];
__device__ float  g_E2  [N_NODES];
__device__ float  g_part[KSPLIT * N_NODES * F_OUT];
__device__ float  g_zp  [KSPLIT * N_NODES];

// ---------------- PTX helpers (baseline, sm_80+) ---------------------------
__device__ __forceinline__ void ldsm_x4(uint32_t* r, uint32_t addr) {
    asm volatile("ldmatrix.sync.aligned.m8n8.x4.shared.b16 {%0,%1,%2,%3}, [%4];"
                 : "=r"(r[0]), "=r"(r[1]), "=r"(r[2]), "=r"(r[3]) : "r"(addr));
}
__device__ __forceinline__ void ldsm_x4_t(uint32_t* r, uint32_t addr) {
    asm volatile("ldmatrix.sync.aligned.m8n8.x4.trans.shared.b16 {%0,%1,%2,%3}, [%4];"
                 : "=r"(r[0]), "=r"(r[1]), "=r"(r[2]), "=r"(r[3]) : "r"(addr));
}
__device__ __forceinline__ void mma16816(float* c, const uint32_t* a,
                                         uint32_t b0, uint32_t b1) {
    asm volatile(
        "mma.sync.aligned.m16n8k16.row.col.f32.f16.f16.f32 "
        "{%0,%1,%2,%3}, {%4,%5,%6,%7}, {%8,%9}, {%0,%1,%2,%3};"
        : "+f"(c[0]), "+f"(c[1]), "+f"(c[2]), "+f"(c[3])
        : "r"(a[0]), "r"(a[1]), "r"(a[2]), "r"(a[3]), "r"(b0), "r"(b1));
}
__device__ __forceinline__ void cp_async16(uint32_t dst, const void* src) {
    asm volatile("cp.async.cg.shared.global [%0], [%1], 16;" :: "r"(dst), "l"(src));
}
#define CP_COMMIT() asm volatile("cp.async.commit_group;" ::: "memory")
#define CP_WAIT0()  asm volatile("cp.async.wait_group 0;" ::: "memory")

// ---------------- kernel 0: fp32 -> fp16 convert (x and W) -----------------
__global__ void __launch_bounds__(256) k_cvt(const float* __restrict__ x,
                                             const float* __restrict__ W,
                                             __half* __restrict__ x16,
                                             __half* __restrict__ W16) {
    const int b = blockIdx.x;
    const float* src;
    __half* dst;
    int i;
    if (b < (N_NODES * F_IN / 1024)) {            // 2048 blocks for x
        i = b * 1024 + threadIdx.x * 4;
        src = x; dst = x16;
    } else {                                      // 32 blocks for W
        i = (b - N_NODES * F_IN / 1024) * 1024 + threadIdx.x * 4;
        src = W; dst = W16;
    }
    float4 v = *(const float4*)&src[i];
    __half2 p01 = __floats2half2_rn(v.x, v.y);
    __half2 p23 = __floats2half2_rn(v.z, v.w);
    uint2 hv;
    hv.x = *reinterpret_cast<uint32_t*>(&p01);
    hv.y = *reinterpret_cast<uint32_t*>(&p23);
    *reinterpret_cast<uint2*>(&dst[i]) = hv;
}

// -------- kernel 1: h16 = x16@W16 (HMMA); s,t + exp factors from fragments -
#define GB_BM 128
#define GB_BK 64
#define GB_NCH (F_IN / GB_BK)          // 4
#define XS_STRIDE 72                   // halves per row (64 + 8 pad)
#define WS_STRIDE 136                  // halves per row (128 + 8 pad)
#define XS_BUF (GB_BM * XS_STRIDE)
#define SMEM_GH (F_IN * WS_STRIDE * 2 + 2 * XS_BUF * 2)

__global__ void __launch_bounds__(256, 1) k_gemm_h(const __half* __restrict__ x16,
                                                   const __half* __restrict__ W16,
                                                   const float* __restrict__ a,
                                                   __half* __restrict__ h16,
                                                   float* __restrict__ F1,
                                                   float* __restrict__ F2,
                                                   float* __restrict__ E1,
                                                   float* __restrict__ E2) {
    extern __shared__ char smem[];
    __half* Ws = (__half*)smem;                        // [256][136]
    __half* Xs = (__half*)(smem + F_IN * WS_STRIDE * 2); // [2][128][72]

    const int tid  = threadIdx.x;
    const int wid  = tid >> 5;
    const int lane = tid & 31;
    const int rowBase = blockIdx.x * GB_BM;

    const uint32_t wsBase = (uint32_t)__cvta_generic_to_shared(Ws);
    const uint32_t xsBase = (uint32_t)__cvta_generic_to_shared(Xs);
    const uint32_t aAddr0 = xsBase + (uint32_t)((wid * 16 + (lane & 15)) * (XS_STRIDE * 2))
                                   + (uint32_t)((lane >> 4) * 16);

    // ---- async W load (whole 256x128, once) ----
#pragma unroll
    for (int i = 0; i < 16; i++) {
        int idx = tid + i * 256;               // 4096 granules of 16B
        int r = idx >> 4;
        int g = idx & 15;
        cp_async16(wsBase + (uint32_t)(r * (WS_STRIDE * 2) + g * 16),
                   (const char*)(W16 + (size_t)r * F_OUT) + g * 16);
    }
    // ---- async X chunk fill ----
    auto fillX = [&](int c, int buf) {
        const uint32_t xb = xsBase + (uint32_t)(buf * XS_BUF * 2);
#pragma unroll
        for (int i = 0; i < 4; i++) {
            int idx = tid + i * 256;           // 1024 granules
            int r = idx >> 3;
            int g = idx & 7;
            cp_async16(xb + (uint32_t)(r * (XS_STRIDE * 2) + g * 16),
                       (const char*)(x16 + (size_t)(rowBase + r) * F_IN + c * GB_BK) + g * 16);
        }
    };

    float acc[16][4];
#pragma unroll
    for (int i = 0; i < 16; i++)
#pragma unroll
        for (int j = 0; j < 4; j++) acc[i][j] = 0.f;

    fillX(0, 0);
    CP_COMMIT();
    CP_WAIT0();
    __syncthreads();

    for (int c = 0; c < GB_NCH; c++) {
        const int cb = c & 1;
        const bool pre = (c + 1 < GB_NCH);
        if (pre) { fillX(c + 1, cb ^ 1); CP_COMMIT(); }
        const uint32_t psB = aAddr0 + (uint32_t)(cb * XS_BUF * 2);
#pragma unroll
        for (int kt = 0; kt < 4; kt++) {
            uint32_t afr[4];
            ldsm_x4(afr, psB + kt * 32);
            const uint32_t bRowAddr = wsBase
                + (uint32_t)((c * GB_BK + kt * 16 + (lane & 15)) * (WS_STRIDE * 2))
                + (uint32_t)((lane >> 4) * 16);
#pragma unroll
            for (int np = 0; np < 8; np++) {
                uint32_t b[4];
                ldsm_x4_t(b, bRowAddr + np * 32);
                mma16816(acc[np * 2 + 0], afr, b[0], b[1]);
                mma16816(acc[np * 2 + 1], afr, b[2], b[3]);
            }
        }
        if (pre) CP_WAIT0();
        __syncthreads();
    }

    // ---- epilogue: h16 stores + s,t from fragments ----
    const int r0 = rowBase + wid * 16 + (lane >> 2);
    const int c0 = (lane & 3) * 2;
    float s0 = 0.f, t0 = 0.f, s1 = 0.f, t1 = 0.f;
#pragma unroll
    for (int nt = 0; nt < 16; nt++) {
        const int col = nt * 8 + c0;
        // h16 stores (half2)
        __half2 hv0 = __floats2half2_rn(acc[nt][0], acc[nt][1]);
        __half2 hv1 = __floats2half2_rn(acc[nt][2], acc[nt][3]);
        *reinterpret_cast<__half2*>(&h16[(size_t)r0 * F_OUT + col]) = hv0;
        *reinterpret_cast<__half2*>(&h16[(size_t)(r0 + 8) * F_OUT + col]) = hv1;
        // s,t partials
        float a1x = a[col], a1y = a[col + 1];
        float a2x = a[F_OUT + col], a2y = a[F_OUT + col + 1];
        s0 += acc[nt][0] * a1x + acc[nt][1] * a1y;
        t0 += acc[nt][0] * a2x + acc[nt][1] * a2y;
        s1 += acc[nt][2] * a1x + acc[nt][3] * a1y;
        t1 += acc[nt][2] * a2x + acc[nt][3] * a2y;
    }
    // reduce across the 4 lanes of each quad (lane&3)
#pragma unroll
    for (int off = 1; off <= 2; off <<= 1) {
        s0 += __shfl_xor_sync(0xffffffffu, s0, off);
        t0 += __shfl_xor_sync(0xffffffffu, t0, off);
        s1 += __shfl_xor_sync(0xffffffffu, s1, off);
        t1 += __shfl_xor_sync(0xffffffffu, t1, off);
    }
    if ((lane & 3) == 0) {
        F1[r0] = __expf(s0 - 4.0f);
        F2[r0] = __expf(0.2f * s0 - 4.0f);
        E1[r0] = __expf(t0 - 4.0f);
        E2[r0] = __expf(0.2f * t0 - 4.0f);
        F1[r0 + 8] = __expf(s1 - 4.0f);
        F2[r0 + 8] = __expf(0.2f * s1 - 4.0f);
        E1[r0 + 8] = __expf(t1 - 4.0f);
        E2[r0 + 8] = __expf(0.2f * t1 - 4.0f);
    }
}

// ---------------- kernel 2: fused P-compute + P@H (HMMA) + Z ---------------
#define BK     64
#define KCOLS  (N_NODES / KSPLIT)
#define NCHUNK (KCOLS / BK)
#define PS_STRIDE 72
#define HS_STRIDE 136
#define PS_BUF (128 * PS_STRIDE)
#define HS_BUF (BK * HS_STRIDE)
#define SMEM_F  (2 * PS_BUF * 2 + 2 * HS_BUF * 2)
#define SMEM_AV (SMEM_F + 2 * 128 * 4)

__global__ void __launch_bounds__(256, 2) k_av_mma(const int* __restrict__ adj,
                                                   const __half* __restrict__ h16,
                                                   const float* __restrict__ F1,
                                                   const float* __restrict__ F2,
                                                   const float* __restrict__ E1,
                                                   const float* __restrict__ E2,
                                                   float* __restrict__ part,
                                                   float* __restrict__ zp) {
    extern __shared__ char smem[];
    __half* Ps  = (__half*)smem;
    __half* Hs  = (__half*)(smem + 2 * PS_BUF * 2);
    float*  sF1 = (float*)(smem + SMEM_F);
    float*  sF2 = sF1 + 128;

    const int tid  = threadIdx.x;
    const int wid  = tid >> 5;
    const int lane = tid & 31;
    const int rowBase = (blockIdx.x >> 2) * 128;
    const int kh      = blockIdx.x & 3;
    const int jBase   = kh * KCOLS;

    if (tid < 128) {
        sF1[tid] = F1[rowBase + tid];
        sF2[tid] = F2[rowBase + tid];
    }

    const int jc   = (lane & 15) * 4;
    const int rsub = lane >> 4;

    const uint32_t psBase = (uint32_t)__cvta_generic_to_shared(Ps);
    const uint32_t hsBase = (uint32_t)__cvta_generic_to_shared(Hs);
    const uint32_t aAddr0 = psBase + (uint32_t)((wid * 16 + (lane & 15)) * (PS_STRIDE * 2))
                                   + (uint32_t)((lane >> 4) * 16);

    float acc[16][4];
#pragma unroll
    for (int i = 0; i < 16; i++)
#pragma unroll
        for (int j = 0; j < 4; j++) acc[i][j] = 0.f;
    float z[8];
#pragma unroll
    for (int p = 0; p < 8; p++) z[p] = 0.f;

    auto ldA4 = [&](int4* av, int pbase, int c) {
        const int j0 = jBase + c * BK;
#pragma unroll
        for (int p = 0; p < 4; p++) {
            const int row = wid * 16 + (pbase + p) * 2 + rsub;
            av[p] = *(const int4*)&adj[(size_t)(rowBase + row) * N_NODES + j0 + jc];
        }
    };
    auto convP4 = [&](const int4* av, int pbase, int buf,
                      float4 e1v, float4 e2v) {
        __half* pb = Ps + buf * PS_BUF;
#pragma unroll
        for (int p = 0; p < 4; p++) {
            const int row = wid * 16 + (pbase + p) * 2 + rsub;
            const float f1 = sF1[row];
            const float f2 = sF2[row];
            float p0 = fmaxf(f1 * e1v.x, f2 * e2v.x);
            float p1 = fmaxf(f1 * e1v.y, f2 * e2v.y);
            float p2 = fmaxf(f1 * e1v.z, f2 * e2v.z);
            float p3 = fmaxf(f1 * e1v.w, f2 * e2v.w);
            p0 = (av[p].x > 0) ? p0 : 0.f;
            p1 = (av[p].y > 0) ? p1 : 0.f;
            p2 = (av[p].z > 0) ? p2 : 0.f;
            p3 = (av[p].w > 0) ? p3 : 0.f;
            z[pbase + p] += (p0 + p1) + (p2 + p3);
            __half2 h01 = __floats2half2_rn(p0, p1);
            __half2 h23 = __floats2half2_rn(p2, p3);
            uint2 stv;
            stv.x = *reinterpret_cast<uint32_t*>(&h01);
            stv.y = *reinterpret_cast<uint32_t*>(&h23);
            *reinterpret_cast<uint2*>(pb + row * PS_STRIDE + jc) = stv;
        }
    };
    auto fillH_async = [&](int c, int buf) {
        const int j0 = jBase + c * BK;
        const uint32_t hb = hsBase + (uint32_t)(buf * HS_BUF * 2);
#pragma unroll
        for (int i = 0; i < 4; i++) {
            int idx = tid + i * 256;
            int r = idx >> 4;
            int g = idx & 15;
            cp_async16(hb + (uint32_t)(r * (HS_STRIDE * 2) + g * 16),
                       (const char*)(h16 + (size_t)(j0 + r) * F_OUT) + g * 16);
        }
    };
    auto mma2 = [&](int ktBase, int buf) {
        const uint32_t psB = aAddr0 + (uint32_t)(buf * PS_BUF * 2);
        const uint32_t hsB = hsBase + (uint32_t)(buf * HS_BUF * 2);
#pragma unroll
        for (int kt = ktBase; kt < ktBase + 2; kt++) {
            uint32_t afr[4];
            ldsm_x4(afr, psB + kt * 32);
            const uint32_t bRowAddr = hsB
                + (uint32_t)((kt * 16 + (lane & 15)) * (HS_STRIDE * 2))
                + (uint32_t)((lane >> 4) * 16);
#pragma unroll
            for (int np = 0; np < 8; np++) {
                uint32_t b[4];
                ldsm_x4_t(b, bRowAddr + np * 32);
                mma16816(acc[np * 2 + 0], afr, b[0], b[1]);
                mma16816(acc[np * 2 + 1], afr, b[2], b[3]);
            }
        }
    };

    __syncthreads();

    {
        fillH_async(0, 0);
        CP_COMMIT();
        const int j0 = jBase;
        float4 e1v = *(const float4*)&E1[j0 + jc];
        float4 e2v = *(const float4*)&E2[j0 + jc];
        int4 avA[4], avB[4];
        ldA4(avA, 0, 0);
        ldA4(avB, 4, 0);
        convP4(avA, 0, 0, e1v, e2v);
        convP4(avB, 4, 0, e1v, e2v);
        CP_WAIT0();
    }
    __syncthreads();

    for (int c = 0; c < NCHUNK; c++) {
        const int cb = c & 1;
        const int nb = cb ^ 1;
        const bool pre = (c + 1 < NCHUNK);
        float4 e1n, e2n;
        int4 avA[4], avB[4];
        if (pre) {
            fillH_async(c + 1, nb);
            CP_COMMIT();
            const int j0 = jBase + (c + 1) * BK;
            e1n = *(const float4*)&E1[j0 + jc];
            e2n = *(const float4*)&E2[j0 + jc];
            ldA4(avA, 0, c + 1);
        }
        mma2(0, cb);
        if (pre) {
            convP4(avA, 0, nb, e1n, e2n);
            ldA4(avB, 4, c + 1);
        }
        mma2(2, cb);
        if (pre) {
            convP4(avB, 4, nb, e1n, e2n);
            CP_WAIT0();
        }
        __syncthreads();
    }

#pragma unroll
    for (int p = 0; p < 8; p++) {
        float zz = z[p];
        zz += __shfl_xor_sync(0xffffffffu, zz, 1);
        zz += __shfl_xor_sync(0xffffffffu, zz, 2);
        zz += __shfl_xor_sync(0xffffffffu, zz, 4);
        zz += __shfl_xor_sync(0xffffffffu, zz, 8);
        if ((lane & 15) == 0)
            zp[kh * N_NODES + rowBase + wid * 16 + p * 2 + rsub] = zz;
    }

    float* partOut = part + (size_t)kh * N_NODES * F_OUT;
    const int r0 = rowBase + wid * 16 + (lane >> 2);
    const int c0 = (lane & 3) * 2;
#pragma unroll
    for (int nt = 0; nt < 16; nt++) {
        *(float2*)&partOut[(size_t)r0 * F_OUT + nt * 8 + c0] =
            make_float2(acc[nt][0], acc[nt][1]);
        *(float2*)&partOut[(size_t)(r0 + 8) * F_OUT + nt * 8 + c0] =
            make_float2(acc[nt][2], acc[nt][3]);
    }
}

// ---------------- kernel 3: out = sum(parts) / sum(z) ----------------------
__global__ void __launch_bounds__(256) k_reduce(const float* __restrict__ part,
                                                const float* __restrict__ zp,
                                                float* __restrict__ out) {
    int i = (blockIdx.x * 256 + threadIdx.x) * 4;
    int row = i / F_OUT;
    float zs = 0.f;
#pragma unroll
    for (int q = 0; q < KSPLIT; q++) zs += zp[q * N_NODES + row];
    float zinv = 1.f / zs;
    float4 acc = *(const float4*)&part[i];
#pragma unroll
    for (int q = 1; q < KSPLIT; q++) {
        float4 b = *(const float4*)&part[(size_t)q * N_NODES * F_OUT + i];
        acc.x += b.x; acc.y += b.y; acc.z += b.z; acc.w += b.w;
    }
    float4 v = make_float4(acc.x * zinv, acc.y * zinv, acc.z * zinv, acc.w * zinv);
    *(float4*)&out[i] = v;
}

// ---------------- launch ----------------
extern "C" void kernel_launch(void* const* d_in, const int* in_sizes, int n_in,
                              void* d_out, int out_size) {
    const float* x   = (const float*)d_in[0];
    const int*   adj = (const int*)  d_in[1];
    const float* W   = (const float*)d_in[2];
    const float* a   = (const float*)d_in[3];
    float* out = (float*)d_out;

    float *F1, *F2, *E1, *E2, *part, *zp;
    __half *x16, *W16, *h16;
    cudaGetSymbolAddress((void**)&x16,  g_x16);
    cudaGetSymbolAddress((void**)&W16,  g_W16);
    cudaGetSymbolAddress((void**)&h16,  g_h16);
    cudaGetSymbolAddress((void**)&F1,   g_F1);
    cudaGetSymbolAddress((void**)&F2,   g_F2);
    cudaGetSymbolAddress((void**)&E1,   g_E1);
    cudaGetSymbolAddress((void**)&E2,   g_E2);
    cudaGetSymbolAddress((void**)&part, g_part);
    cudaGetSymbolAddress((void**)&zp,   g_zp);

    cudaFuncSetAttribute(k_gemm_h, cudaFuncAttributeMaxDynamicSharedMemorySize, SMEM_GH);
    cudaFuncSetAttribute(k_av_mma, cudaFuncAttributeMaxDynamicSharedMemorySize, SMEM_AV);

    k_cvt    <<<(N_NODES * F_IN + F_IN * F_OUT) / 1024, 256>>>(x, W, x16, W16);
    k_gemm_h <<<N_NODES / GB_BM, 256, SMEM_GH>>>(x16, W16, a, h16, F1, F2, E1, E2);
    k_av_mma <<<(N_NODES / 128) * KSPLIT, 256, SMEM_AV>>>(adj, h16, F1, F2, E1, E2, part, zp);
    k_reduce <<<N_NODES * F_OUT / 1024, 256>>>(part, zp, out);
}